// round 1
// baseline (speedup 1.0000x reference)
#include <cuda_runtime.h>

#define BB 2
#define SS 2048
#define DD 1024
#define HH 16
#define DHD 64
#define BH (BB*HH)

// Scratch: Q (pre-scaled by 1/sqrt(DH)), K transposed [bh][d][s], V. 48MB total.
__device__ float g_Q [BH * SS * DHD];
__device__ float g_KT[BH * DHD * SS];
__device__ float g_V [BH * SS * DHD];

// exp(x) on the FMA/ALU pipes (avoids MUFU bottleneck: 134M exps would cost ~1ms on MUFU).
// x <= 0 in all our uses. rel err ~2e-6.
__device__ __forceinline__ float fast_exp(float x) {
    float y = fmaxf(x * 1.4426950408889634f, -100.0f);   // log2(e), clamp (2^-100 ~= 0)
    float z = y + 12582912.0f;                           // round-to-nearest-int via magic
    int   n = __float_as_int(z) - 0x4B400000;
    float f = y - (z - 12582912.0f);                     // f in [-0.5, 0.5]
    float p = 1.33335581e-3f;
    p = fmaf(p, f, 9.61812911e-3f);
    p = fmaf(p, f, 5.55041087e-2f);
    p = fmaf(p, f, 2.40226507e-1f);
    p = fmaf(p, f, 6.93147181e-1f);
    p = fmaf(p, f, 1.0f);
    return __int_as_float(__float_as_int(p) + (n << 23)); // * 2^n
}

// ---------------------------------------------------------------------------
// Kernel 1: fused Q/K/V projection.
// grid (S/64, BH), 256 threads. Each block: X tile [64x1024] x W[1024x64] x3.
// Q stored scaled by 0.125 (=1/sqrt(64)). K stored transposed [bh][d][s].
// ---------------------------------------------------------------------------
__global__ __launch_bounds__(256) void qkv_proj(
    const float* __restrict__ X,
    const float* __restrict__ Wq, const float* __restrict__ bq,
    const float* __restrict__ Wk, const float* __restrict__ bk,
    const float* __restrict__ Wv, const float* __restrict__ bv)
{
    const int stile = blockIdx.x;          // 0..31
    const int bh    = blockIdx.y;          // 0..31
    const int b     = bh / HH, h = bh % HH;
    const int tid   = threadIdx.x;
    const int ty    = tid >> 4;            // 0..15 -> rows 4*ty..4*ty+3
    const int tx    = tid & 15;            // 0..15 -> cols 4*tx..4*tx+3

    __shared__ float sX [64 * 36];         // 64 rows x 32 cols, pad to 36 (16B-aligned rows)
    __shared__ float sWq[32 * 64];
    __shared__ float sWk[32 * 64];
    __shared__ float sWv[32 * 64];

    float aq[4][4] = {}, ak[4][4] = {}, av[4][4] = {};

    const float* Xb  = X  + ((size_t)b * SS + (size_t)stile * 64) * DD;
    const float* Wqh = Wq + (size_t)h * DD * DHD;
    const float* Wkh = Wk + (size_t)h * DD * DHD;
    const float* Wvh = Wv + (size_t)h * DD * DHD;

    for (int k0 = 0; k0 < DD; k0 += 32) {
        __syncthreads();
        // X tile 64x32: 512 float4, 2 per thread
        for (int v = tid; v < 64 * 8; v += 256) {
            int r = v >> 3, c4 = v & 7;
            *(float4*)&sX[r * 36 + c4 * 4] =
                *(const float4*)&Xb[(size_t)r * DD + k0 + c4 * 4];
        }
        // W tiles 32x64 each: 512 float4, 2 per thread per matrix
        for (int v = tid; v < 32 * 16; v += 256) {
            int r = v >> 4, c4 = v & 15;
            int go = (k0 + r) * DHD + c4 * 4;
            int so = r * 64 + c4 * 4;
            *(float4*)&sWq[so] = *(const float4*)&Wqh[go];
            *(float4*)&sWk[so] = *(const float4*)&Wkh[go];
            *(float4*)&sWv[so] = *(const float4*)&Wvh[go];
        }
        __syncthreads();

        #pragma unroll 4
        for (int kk = 0; kk < 32; kk++) {
            float xv[4];
            #pragma unroll
            for (int i = 0; i < 4; i++) xv[i] = sX[(ty * 4 + i) * 36 + kk];
            float4 wq = *(const float4*)&sWq[kk * 64 + tx * 4];
            float4 wk = *(const float4*)&sWk[kk * 64 + tx * 4];
            float4 wv = *(const float4*)&sWv[kk * 64 + tx * 4];
            #pragma unroll
            for (int i = 0; i < 4; i++) {
                aq[i][0] = fmaf(xv[i], wq.x, aq[i][0]);
                aq[i][1] = fmaf(xv[i], wq.y, aq[i][1]);
                aq[i][2] = fmaf(xv[i], wq.z, aq[i][2]);
                aq[i][3] = fmaf(xv[i], wq.w, aq[i][3]);
                ak[i][0] = fmaf(xv[i], wk.x, ak[i][0]);
                ak[i][1] = fmaf(xv[i], wk.y, ak[i][1]);
                ak[i][2] = fmaf(xv[i], wk.z, ak[i][2]);
                ak[i][3] = fmaf(xv[i], wk.w, ak[i][3]);
                av[i][0] = fmaf(xv[i], wv.x, av[i][0]);
                av[i][1] = fmaf(xv[i], wv.y, av[i][1]);
                av[i][2] = fmaf(xv[i], wv.z, av[i][2]);
                av[i][3] = fmaf(xv[i], wv.w, av[i][3]);
            }
        }
    }

    // Epilogue: add bias, store. Q scaled by 0.125 (softmax scale folded in).
    const int s0 = stile * 64;
    float4 bq4 = *(const float4*)&bq[h * DHD + tx * 4];
    float4 bk4 = *(const float4*)&bk[h * DHD + tx * 4];
    float4 bv4 = *(const float4*)&bv[h * DHD + tx * 4];
    float bka[4] = {bk4.x, bk4.y, bk4.z, bk4.w};

    #pragma unroll
    for (int i = 0; i < 4; i++) {
        int row = s0 + ty * 4 + i;
        float4 oq, ov;
        oq.x = (aq[i][0] + bq4.x) * 0.125f;
        oq.y = (aq[i][1] + bq4.y) * 0.125f;
        oq.z = (aq[i][2] + bq4.z) * 0.125f;
        oq.w = (aq[i][3] + bq4.w) * 0.125f;
        ov.x = av[i][0] + bv4.x;
        ov.y = av[i][1] + bv4.y;
        ov.z = av[i][2] + bv4.z;
        ov.w = av[i][3] + bv4.w;
        *(float4*)&g_Q[((size_t)bh * SS + row) * DHD + tx * 4] = oq;
        *(float4*)&g_V[((size_t)bh * SS + row) * DHD + tx * 4] = ov;
    }
    // K transposed: for each owned col, contiguous 4 rows -> float4
    #pragma unroll
    for (int j = 0; j < 4; j++) {
        int c = tx * 4 + j;
        float4 ok;
        ok.x = ak[0][j] + bka[j];
        ok.y = ak[1][j] + bka[j];
        ok.z = ak[2][j] + bka[j];
        ok.w = ak[3][j] + bka[j];
        *(float4*)&g_KT[((size_t)bh * DHD + c) * SS + s0 + ty * 4] = ok;
    }
}

// ---------------------------------------------------------------------------
// Kernel 2: attention with full-row softmax + post-softmax causal mask.
// grid (S/64, BH), 256 threads. Per block: 64 query rows, loop over 32 k-tiles.
// Denominator accumulates ALL columns; numerator only t <= s.
// P·V skipped entirely for fully-masked tiles (kt > qt).
// ---------------------------------------------------------------------------
__global__ __launch_bounds__(256) void attn(float* __restrict__ out)
{
    const int qt  = blockIdx.x;            // 0..31
    const int bh  = blockIdx.y;            // 0..31
    const int b   = bh / HH, h = bh % HH;
    const int tid = threadIdx.x;
    const int ty  = tid >> 4;              // rows 4*ty..4*ty+3
    const int tx  = tid & 15;              // cols 4*tx..4*tx+3

    __shared__ float sQ[64 * 64];
    __shared__ float sK[64 * 64];          // K^T tile [d][j]; reused as P after QK
    __shared__ float sV[64 * 64];          // V tile [j][e]

    // Load Q tile (already scaled by 1/sqrt(DH))
    const float* Qb = g_Q + ((size_t)bh * SS + (size_t)qt * 64) * DHD;
    for (int v = tid; v < 64 * 16; v += 256) {
        int r = v >> 4, c4 = v & 15;
        *(float4*)&sQ[r * 64 + c4 * 4] = *(const float4*)&Qb[(size_t)r * DHD + c4 * 4];
    }

    float acc[4][4] = {};
    float m[4] = {-1e30f, -1e30f, -1e30f, -1e30f};
    float l[4] = {};

    const float* KTb = g_KT + (size_t)bh * DHD * SS;
    const float* Vb  = g_V  + (size_t)bh * SS * DHD;

    for (int kt = 0; kt < SS / 64; kt++) {
        __syncthreads();   // previous iter's P·V reads of sK/sV complete
        for (int v = tid; v < 64 * 16; v += 256) {
            int r = v >> 4, c4 = v & 15;
            *(float4*)&sK[r * 64 + c4 * 4] =
                *(const float4*)&KTb[(size_t)r * SS + kt * 64 + c4 * 4];
            *(float4*)&sV[r * 64 + c4 * 4] =
                *(const float4*)&Vb[((size_t)kt * 64 + r) * DHD + c4 * 4];
        }
        __syncthreads();

        // S = Q @ K^T  (scores, scale already folded into Q)
        float p[4][4] = {};
        #pragma unroll 8
        for (int d = 0; d < 64; d++) {
            float4 kv = *(const float4*)&sK[d * 64 + tx * 4];
            #pragma unroll
            for (int i = 0; i < 4; i++) {
                float q = sQ[(ty * 4 + i) * 64 + d];
                p[i][0] = fmaf(q, kv.x, p[i][0]);
                p[i][1] = fmaf(q, kv.y, p[i][1]);
                p[i][2] = fmaf(q, kv.z, p[i][2]);
                p[i][3] = fmaf(q, kv.w, p[i][3]);
            }
        }

        // Online softmax (full-row stats: unmasked sum into l)
        float fac[4];
        #pragma unroll
        for (int i = 0; i < 4; i++) {
            float rmax = fmaxf(fmaxf(p[i][0], p[i][1]), fmaxf(p[i][2], p[i][3]));
            rmax = fmaxf(rmax, __shfl_xor_sync(0xffffffffu, rmax, 8));
            rmax = fmaxf(rmax, __shfl_xor_sync(0xffffffffu, rmax, 4));
            rmax = fmaxf(rmax, __shfl_xor_sync(0xffffffffu, rmax, 2));
            rmax = fmaxf(rmax, __shfl_xor_sync(0xffffffffu, rmax, 1));
            float mnew = fmaxf(m[i], rmax);
            fac[i] = fast_exp(m[i] - mnew);
            m[i] = mnew;
            float rs = 0.f;
            #pragma unroll
            for (int jj = 0; jj < 4; jj++) {
                p[i][jj] = fast_exp(p[i][jj] - mnew);
                rs += p[i][jj];
            }
            rs += __shfl_xor_sync(0xffffffffu, rs, 8);
            rs += __shfl_xor_sync(0xffffffffu, rs, 4);
            rs += __shfl_xor_sync(0xffffffffu, rs, 2);
            rs += __shfl_xor_sync(0xffffffffu, rs, 1);
            l[i] = l[i] * fac[i] + rs;
            #pragma unroll
            for (int jj = 0; jj < 4; jj++) acc[i][jj] *= fac[i];
        }

        if (kt <= qt) {      // tile has at least one unmasked column
            __syncthreads(); // all QK reads of sK done before overwrite with P
            #pragma unroll
            for (int i = 0; i < 4; i++) {
                int qrow = qt * 64 + ty * 4 + i;
                int kc   = kt * 64 + tx * 4;
                float4 w;
                w.x = (kc + 0 <= qrow) ? p[i][0] : 0.f;
                w.y = (kc + 1 <= qrow) ? p[i][1] : 0.f;
                w.z = (kc + 2 <= qrow) ? p[i][2] : 0.f;
                w.w = (kc + 3 <= qrow) ? p[i][3] : 0.f;
                *(float4*)&sK[(ty * 4 + i) * 64 + tx * 4] = w;
            }
            __syncthreads();
            // acc += P @ V
            #pragma unroll 8
            for (int j = 0; j < 64; j++) {
                float4 vv = *(const float4*)&sV[j * 64 + tx * 4];
                #pragma unroll
                for (int i = 0; i < 4; i++) {
                    float pp = sK[(ty * 4 + i) * 64 + j];
                    acc[i][0] = fmaf(pp, vv.x, acc[i][0]);
                    acc[i][1] = fmaf(pp, vv.y, acc[i][1]);
                    acc[i][2] = fmaf(pp, vv.z, acc[i][2]);
                    acc[i][3] = fmaf(pp, vv.w, acc[i][3]);
                }
            }
        }
    }

    // Epilogue: divide by full-row denominator, write out[b, s, h*64+e]
    float* outb = out + ((size_t)b * SS + (size_t)qt * 64) * (HH * DHD) + h * DHD;
    #pragma unroll
    for (int i = 0; i < 4; i++) {
        float inv = 1.0f / l[i];
        float4 o;
        o.x = acc[i][0] * inv;
        o.y = acc[i][1] * inv;
        o.z = acc[i][2] * inv;
        o.w = acc[i][3] * inv;
        *(float4*)&outb[(size_t)(ty * 4 + i) * (HH * DHD) + tx * 4] = o;
    }
}

extern "C" void kernel_launch(void* const* d_in, const int* in_sizes, int n_in,
                              void* d_out, int out_size) {
    const float* X  = (const float*)d_in[0];
    const float* Wq = (const float*)d_in[1];
    const float* bq = (const float*)d_in[2];
    const float* Wk = (const float*)d_in[3];
    const float* bk = (const float*)d_in[4];
    const float* Wv = (const float*)d_in[5];
    const float* bv = (const float*)d_in[6];
    float* out = (float*)d_out;

    dim3 blk(256);
    dim3 g1(SS / 64, BH);
    qkv_proj<<<g1, blk>>>(X, Wq, bq, Wk, bk, Wv, bv);
    dim3 g2(SS / 64, BH);
    attn<<<g2, blk>>>(out);
}

// round 2
// speedup vs baseline: 1.0065x; 1.0065x over previous
#include <cuda_runtime.h>

#define BB 2
#define SS 2048
#define DD 1024
#define HH 16
#define DHD 64
#define BH (BB*HH)

// Scratch: Q (pre-scaled by 1/sqrt(DH)), K transposed [bh][d][s], V. 48MB total.
__device__ float g_Q [BH * SS * DHD];
__device__ float g_KT[BH * DHD * SS];
__device__ float g_V [BH * SS * DHD];

// exp(x) on the FMA/ALU pipes (avoids MUFU bottleneck: 134M exps would cost ~1ms on MUFU).
// x <= 0 in all our uses. rel err ~2e-6.
__device__ __forceinline__ float fast_exp(float x) {
    float y = fmaxf(x * 1.4426950408889634f, -100.0f);   // log2(e), clamp (2^-100 ~= 0)
    float z = y + 12582912.0f;                           // round-to-nearest-int via magic
    int   n = __float_as_int(z) - 0x4B400000;
    float f = y - (z - 12582912.0f);                     // f in [-0.5, 0.5]
    float p = 1.33335581e-3f;
    p = fmaf(p, f, 9.61812911e-3f);
    p = fmaf(p, f, 5.55041087e-2f);
    p = fmaf(p, f, 2.40226507e-1f);
    p = fmaf(p, f, 6.93147181e-1f);
    p = fmaf(p, f, 1.0f);
    return __int_as_float(__float_as_int(p) + (n << 23)); // * 2^n
}

// ---------------------------------------------------------------------------
// Kernel 1: fused Q/K/V projection.
// grid (S/64, BH), 256 threads. Each block: X tile [64x1024] x W[1024x64] x3.
// Q stored scaled by 0.125 (=1/sqrt(64)). K stored transposed [bh][d][s].
// ---------------------------------------------------------------------------
__global__ __launch_bounds__(256) void qkv_proj(
    const float* __restrict__ X,
    const float* __restrict__ Wq, const float* __restrict__ bq,
    const float* __restrict__ Wk, const float* __restrict__ bk,
    const float* __restrict__ Wv, const float* __restrict__ bv)
{
    const int stile = blockIdx.x;          // 0..31
    const int bh    = blockIdx.y;          // 0..31
    const int b     = bh / HH, h = bh % HH;
    const int tid   = threadIdx.x;
    const int ty    = tid >> 4;            // 0..15 -> rows 4*ty..4*ty+3
    const int tx    = tid & 15;            // 0..15 -> cols 4*tx..4*tx+3

    __shared__ float sX [64 * 36];         // 64 rows x 32 cols, pad to 36 (16B-aligned rows)
    __shared__ float sWq[32 * 64];
    __shared__ float sWk[32 * 64];
    __shared__ float sWv[32 * 64];

    float aq[4][4] = {}, ak[4][4] = {}, av[4][4] = {};

    const float* Xb  = X  + ((size_t)b * SS + (size_t)stile * 64) * DD;
    const float* Wqh = Wq + (size_t)h * DD * DHD;
    const float* Wkh = Wk + (size_t)h * DD * DHD;
    const float* Wvh = Wv + (size_t)h * DD * DHD;

    for (int k0 = 0; k0 < DD; k0 += 32) {
        __syncthreads();
        // X tile 64x32: 512 float4, 2 per thread
        for (int v = tid; v < 64 * 8; v += 256) {
            int r = v >> 3, c4 = v & 7;
            *(float4*)&sX[r * 36 + c4 * 4] =
                *(const float4*)&Xb[(size_t)r * DD + k0 + c4 * 4];
        }
        // W tiles 32x64 each: 512 float4, 2 per thread per matrix
        for (int v = tid; v < 32 * 16; v += 256) {
            int r = v >> 4, c4 = v & 15;
            int go = (k0 + r) * DHD + c4 * 4;
            int so = r * 64 + c4 * 4;
            *(float4*)&sWq[so] = *(const float4*)&Wqh[go];
            *(float4*)&sWk[so] = *(const float4*)&Wkh[go];
            *(float4*)&sWv[so] = *(const float4*)&Wvh[go];
        }
        __syncthreads();

        #pragma unroll 4
        for (int kk = 0; kk < 32; kk++) {
            float xv[4];
            #pragma unroll
            for (int i = 0; i < 4; i++) xv[i] = sX[(ty * 4 + i) * 36 + kk];
            float4 wq = *(const float4*)&sWq[kk * 64 + tx * 4];
            float4 wk = *(const float4*)&sWk[kk * 64 + tx * 4];
            float4 wv = *(const float4*)&sWv[kk * 64 + tx * 4];
            #pragma unroll
            for (int i = 0; i < 4; i++) {
                aq[i][0] = fmaf(xv[i], wq.x, aq[i][0]);
                aq[i][1] = fmaf(xv[i], wq.y, aq[i][1]);
                aq[i][2] = fmaf(xv[i], wq.z, aq[i][2]);
                aq[i][3] = fmaf(xv[i], wq.w, aq[i][3]);
                ak[i][0] = fmaf(xv[i], wk.x, ak[i][0]);
                ak[i][1] = fmaf(xv[i], wk.y, ak[i][1]);
                ak[i][2] = fmaf(xv[i], wk.z, ak[i][2]);
                ak[i][3] = fmaf(xv[i], wk.w, ak[i][3]);
                av[i][0] = fmaf(xv[i], wv.x, av[i][0]);
                av[i][1] = fmaf(xv[i], wv.y, av[i][1]);
                av[i][2] = fmaf(xv[i], wv.z, av[i][2]);
                av[i][3] = fmaf(xv[i], wv.w, av[i][3]);
            }
        }
    }

    // Epilogue: add bias, store. Q scaled by 0.125 (softmax scale folded in).
    const int s0 = stile * 64;
    float4 bq4 = *(const float4*)&bq[h * DHD + tx * 4];
    float4 bk4 = *(const float4*)&bk[h * DHD + tx * 4];
    float4 bv4 = *(const float4*)&bv[h * DHD + tx * 4];
    float bka[4] = {bk4.x, bk4.y, bk4.z, bk4.w};

    #pragma unroll
    for (int i = 0; i < 4; i++) {
        int row = s0 + ty * 4 + i;
        float4 oq, ov;
        oq.x = (aq[i][0] + bq4.x) * 0.125f;
        oq.y = (aq[i][1] + bq4.y) * 0.125f;
        oq.z = (aq[i][2] + bq4.z) * 0.125f;
        oq.w = (aq[i][3] + bq4.w) * 0.125f;
        ov.x = av[i][0] + bv4.x;
        ov.y = av[i][1] + bv4.y;
        ov.z = av[i][2] + bv4.z;
        ov.w = av[i][3] + bv4.w;
        *(float4*)&g_Q[((size_t)bh * SS + row) * DHD + tx * 4] = oq;
        *(float4*)&g_V[((size_t)bh * SS + row) * DHD + tx * 4] = ov;
    }
    // K transposed: for each owned col, contiguous 4 rows -> float4
    #pragma unroll
    for (int j = 0; j < 4; j++) {
        int c = tx * 4 + j;
        float4 ok;
        ok.x = ak[0][j] + bka[j];
        ok.y = ak[1][j] + bka[j];
        ok.z = ak[2][j] + bka[j];
        ok.w = ak[3][j] + bka[j];
        *(float4*)&g_KT[((size_t)bh * DHD + c) * SS + s0 + ty * 4] = ok;
    }
}

// ---------------------------------------------------------------------------
// Kernel 2: attention with full-row softmax + post-softmax causal mask.
// grid (S/64, BH), 256 threads. Per block: 64 query rows, loop over 32 k-tiles.
// Denominator accumulates ALL columns; numerator only t <= s.
// P·V skipped entirely for fully-masked tiles (kt > qt).
// ---------------------------------------------------------------------------
__global__ __launch_bounds__(256) void attn(float* __restrict__ out)
{
    const int qt  = blockIdx.x;            // 0..31
    const int bh  = blockIdx.y;            // 0..31
    const int b   = bh / HH, h = bh % HH;
    const int tid = threadIdx.x;
    const int ty  = tid >> 4;              // rows 4*ty..4*ty+3
    const int tx  = tid & 15;              // cols 4*tx..4*tx+3

    __shared__ float sQ[64 * 64];
    __shared__ float sK[64 * 64];          // K^T tile [d][j]; reused as P after QK
    __shared__ float sV[64 * 64];          // V tile [j][e]

    // Load Q tile (already scaled by 1/sqrt(DH))
    const float* Qb = g_Q + ((size_t)bh * SS + (size_t)qt * 64) * DHD;
    for (int v = tid; v < 64 * 16; v += 256) {
        int r = v >> 4, c4 = v & 15;
        *(float4*)&sQ[r * 64 + c4 * 4] = *(const float4*)&Qb[(size_t)r * DHD + c4 * 4];
    }

    float acc[4][4] = {};
    float m[4] = {-1e30f, -1e30f, -1e30f, -1e30f};
    float l[4] = {};

    const float* KTb = g_KT + (size_t)bh * DHD * SS;
    const float* Vb  = g_V  + (size_t)bh * SS * DHD;

    for (int kt = 0; kt < SS / 64; kt++) {
        __syncthreads();   // previous iter's P·V reads of sK/sV complete
        for (int v = tid; v < 64 * 16; v += 256) {
            int r = v >> 4, c4 = v & 15;
            *(float4*)&sK[r * 64 + c4 * 4] =
                *(const float4*)&KTb[(size_t)r * SS + kt * 64 + c4 * 4];
            *(float4*)&sV[r * 64 + c4 * 4] =
                *(const float4*)&Vb[((size_t)kt * 64 + r) * DHD + c4 * 4];
        }
        __syncthreads();

        // S = Q @ K^T  (scores, scale already folded into Q)
        float p[4][4] = {};
        #pragma unroll 8
        for (int d = 0; d < 64; d++) {
            float4 kv = *(const float4*)&sK[d * 64 + tx * 4];
            #pragma unroll
            for (int i = 0; i < 4; i++) {
                float q = sQ[(ty * 4 + i) * 64 + d];
                p[i][0] = fmaf(q, kv.x, p[i][0]);
                p[i][1] = fmaf(q, kv.y, p[i][1]);
                p[i][2] = fmaf(q, kv.z, p[i][2]);
                p[i][3] = fmaf(q, kv.w, p[i][3]);
            }
        }

        // Online softmax (full-row stats: unmasked sum into l)
        float fac[4];
        #pragma unroll
        for (int i = 0; i < 4; i++) {
            float rmax = fmaxf(fmaxf(p[i][0], p[i][1]), fmaxf(p[i][2], p[i][3]));
            rmax = fmaxf(rmax, __shfl_xor_sync(0xffffffffu, rmax, 8));
            rmax = fmaxf(rmax, __shfl_xor_sync(0xffffffffu, rmax, 4));
            rmax = fmaxf(rmax, __shfl_xor_sync(0xffffffffu, rmax, 2));
            rmax = fmaxf(rmax, __shfl_xor_sync(0xffffffffu, rmax, 1));
            float mnew = fmaxf(m[i], rmax);
            fac[i] = fast_exp(m[i] - mnew);
            m[i] = mnew;
            float rs = 0.f;
            #pragma unroll
            for (int jj = 0; jj < 4; jj++) {
                p[i][jj] = fast_exp(p[i][jj] - mnew);
                rs += p[i][jj];
            }
            rs += __shfl_xor_sync(0xffffffffu, rs, 8);
            rs += __shfl_xor_sync(0xffffffffu, rs, 4);
            rs += __shfl_xor_sync(0xffffffffu, rs, 2);
            rs += __shfl_xor_sync(0xffffffffu, rs, 1);
            l[i] = l[i] * fac[i] + rs;
            #pragma unroll
            for (int jj = 0; jj < 4; jj++) acc[i][jj] *= fac[i];
        }

        if (kt <= qt) {      // tile has at least one unmasked column
            __syncthreads(); // all QK reads of sK done before overwrite with P
            #pragma unroll
            for (int i = 0; i < 4; i++) {
                int qrow = qt * 64 + ty * 4 + i;
                int kc   = kt * 64 + tx * 4;
                float4 w;
                w.x = (kc + 0 <= qrow) ? p[i][0] : 0.f;
                w.y = (kc + 1 <= qrow) ? p[i][1] : 0.f;
                w.z = (kc + 2 <= qrow) ? p[i][2] : 0.f;
                w.w = (kc + 3 <= qrow) ? p[i][3] : 0.f;
                *(float4*)&sK[(ty * 4 + i) * 64 + tx * 4] = w;
            }
            __syncthreads();
            // acc += P @ V
            #pragma unroll 8
            for (int j = 0; j < 64; j++) {
                float4 vv = *(const float4*)&sV[j * 64 + tx * 4];
                #pragma unroll
                for (int i = 0; i < 4; i++) {
                    float pp = sK[(ty * 4 + i) * 64 + j];
                    acc[i][0] = fmaf(pp, vv.x, acc[i][0]);
                    acc[i][1] = fmaf(pp, vv.y, acc[i][1]);
                    acc[i][2] = fmaf(pp, vv.z, acc[i][2]);
                    acc[i][3] = fmaf(pp, vv.w, acc[i][3]);
                }
            }
        }
    }

    // Epilogue: divide by full-row denominator, write out[b, s, h*64+e]
    float* outb = out + ((size_t)b * SS + (size_t)qt * 64) * (HH * DHD) + h * DHD;
    #pragma unroll
    for (int i = 0; i < 4; i++) {
        float inv = 1.0f / l[i];
        float4 o;
        o.x = acc[i][0] * inv;
        o.y = acc[i][1] * inv;
        o.z = acc[i][2] * inv;
        o.w = acc[i][3] * inv;
        *(float4*)&outb[(size_t)(ty * 4 + i) * (HH * DHD) + tx * 4] = o;
    }
}

extern "C" void kernel_launch(void* const* d_in, const int* in_sizes, int n_in,
                              void* d_out, int out_size) {
    const float* X  = (const float*)d_in[0];
    const float* Wq = (const float*)d_in[1];
    const float* bq = (const float*)d_in[2];
    const float* Wk = (const float*)d_in[3];
    const float* bk = (const float*)d_in[4];
    const float* Wv = (const float*)d_in[5];
    const float* bv = (const float*)d_in[6];
    float* out = (float*)d_out;

    dim3 blk(256);
    dim3 g1(SS / 64, BH);
    qkv_proj<<<g1, blk>>>(X, Wq, bq, Wk, bk, Wv, bv);
    dim3 g2(SS / 64, BH);
    attn<<<g2, blk>>>(out);
}

// round 4
// speedup vs baseline: 2.2141x; 2.1997x over previous
#include <cuda_runtime.h>
#include <cuda_bf16.h>
#include <cstdint>

// ---------------- scratch (device globals) ----------------
__device__ __align__(16) __nv_bfloat16 g_Xh[4096*1024], g_Xl[4096*1024];
__device__ __align__(16) __nv_bfloat16 g_Wh[3*1024*1024], g_Wl[3*1024*1024];
__device__ __align__(16) __nv_bfloat16 g_Qh[32*2048*64], g_Ql[32*2048*64];
__device__ __align__(16) __nv_bfloat16 g_Kh[32*2048*64], g_Kl[32*2048*64];
__device__ __align__(16) __nv_bfloat16 g_Vh[32*2048*64], g_Vl[32*2048*64];

// ---------------- helpers ----------------
__device__ __forceinline__ uint32_t smem_u32(const void* p) {
    uint32_t a;
    asm("{ .reg .u64 t; cvta.to.shared.u64 t, %1; cvt.u32.u64 %0, t; }" : "=r"(a) : "l"(p));
    return a;
}
__device__ __forceinline__ uint32_t packbf(__nv_bfloat16 a, __nv_bfloat16 b) {
    return (uint32_t)*(uint16_t*)&a | ((uint32_t)*(uint16_t*)&b << 16);
}
__device__ __forceinline__ void split2(float a, float b, uint32_t& hw, uint32_t& lw) {
    __nv_bfloat16 ha = __float2bfloat16(a), hb = __float2bfloat16(b);
    hw = packbf(ha, hb);
    lw = packbf(__float2bfloat16(a - __bfloat162float(ha)),
                __float2bfloat16(b - __bfloat162float(hb)));
}
__device__ __forceinline__ float fast_exp(float x) {
    float y = fmaxf(x * 1.4426950408889634f, -100.0f);
    float z = y + 12582912.0f;
    int   n = __float_as_int(z) - 0x4B400000;
    float f = y - (z - 12582912.0f);
    float p = 1.33335581e-3f;
    p = fmaf(p, f, 9.61812911e-3f);
    p = fmaf(p, f, 5.55041087e-2f);
    p = fmaf(p, f, 2.40226507e-1f);
    p = fmaf(p, f, 6.93147181e-1f);
    p = fmaf(p, f, 1.0f);
    return __int_as_float(__float_as_int(p) + (n << 23));
}
__device__ __forceinline__ void ldsm_x4(uint32_t a, uint32_t& r0, uint32_t& r1,
                                        uint32_t& r2, uint32_t& r3) {
    asm volatile("ldmatrix.sync.aligned.m8n8.x4.shared.b16 {%0,%1,%2,%3}, [%4];"
        : "=r"(r0), "=r"(r1), "=r"(r2), "=r"(r3) : "r"(a));
}
__device__ __forceinline__ void ldsm_x2(uint32_t a, uint32_t& r0, uint32_t& r1) {
    asm volatile("ldmatrix.sync.aligned.m8n8.x2.shared.b16 {%0,%1}, [%2];"
        : "=r"(r0), "=r"(r1) : "r"(a));
}
__device__ __forceinline__ void ldsm_x2t(uint32_t a, uint32_t& r0, uint32_t& r1) {
    asm volatile("ldmatrix.sync.aligned.m8n8.x2.trans.shared.b16 {%0,%1}, [%2];"
        : "=r"(r0), "=r"(r1) : "r"(a));
}
__device__ __forceinline__ void mma16816(float* c, uint32_t a0, uint32_t a1,
                                         uint32_t a2, uint32_t a3,
                                         uint32_t b0, uint32_t b1) {
    asm volatile("mma.sync.aligned.m16n8k16.row.col.f32.bf16.bf16.f32 "
        "{%0,%1,%2,%3}, {%4,%5,%6,%7}, {%8,%9}, {%0,%1,%2,%3};"
        : "+f"(c[0]), "+f"(c[1]), "+f"(c[2]), "+f"(c[3])
        : "r"(a0), "r"(a1), "r"(a2), "r"(a3), "r"(b0), "r"(b1));
}

// ---------------- prep: split X to bf16 hi/lo ----------------
__global__ __launch_bounds__(256) void prep_x(const float* __restrict__ X) {
    size_t i = (size_t)blockIdx.x * 256 + threadIdx.x;   // 1,048,576 float4
    float4 v = ((const float4*)X)[i];
    uint32_t h0, l0, h1, l1;
    split2(v.x, v.y, h0, l0);
    split2(v.z, v.w, h1, l1);
    ((uint2*)g_Xh)[i] = make_uint2(h0, h1);
    ((uint2*)g_Xl)[i] = make_uint2(l0, l1);
}

// ---------------- prep: transpose+split W -> [mat][h*64+e][d] ----------------
__global__ __launch_bounds__(256) void prep_w(const float* __restrict__ Wq,
                                              const float* __restrict__ Wk,
                                              const float* __restrict__ Wv) {
    int z = blockIdx.z, mat = z >> 4, h = z & 15;
    const float* W = (mat == 0 ? Wq : (mat == 1 ? Wk : Wv)) + (size_t)h * 1024 * 64;
    __shared__ float t[32][33];
    int d0 = blockIdx.x * 32, e0 = blockIdx.y * 32;
    int tx = threadIdx.x, ty = threadIdx.y;                 // 32 x 8
    #pragma unroll
    for (int k = 0; k < 4; k++)
        t[ty + 8 * k][tx] = W[(size_t)(d0 + ty + 8 * k) * 64 + e0 + tx];
    __syncthreads();
    __nv_bfloat16* oh = g_Wh + (size_t)mat * 1024 * 1024;
    __nv_bfloat16* ol = g_Wl + (size_t)mat * 1024 * 1024;
    #pragma unroll
    for (int k = 0; k < 4; k++) {
        int j = ty + 8 * k;
        float v = t[tx][j];
        __nv_bfloat16 hv = __float2bfloat16(v);
        size_t o = (size_t)(h * 64 + e0 + j) * 1024 + d0 + tx;
        oh[o] = hv;
        ol[o] = __float2bfloat16(v - __bfloat162float(hv));
    }
}

// ---------------- QKV GEMM: C[4096x1024] = X · Wt^T, bf16x3 HMMA ----------------
#define PAD 40
__global__ __launch_bounds__(256) void qkv_mm(const float* __restrict__ bq,
                                              const float* __restrict__ bk,
                                              const float* __restrict__ bv) {
    __shared__ __nv_bfloat16 sAh[128*PAD], sAl[128*PAD], sBh[128*PAD], sBl[128*PAD];
    int tid = threadIdx.x, lane = tid & 31, wid = tid >> 5;
    int stile = blockIdx.x, octile = blockIdx.y, mat = blockIdx.z;
    int wm = wid >> 2, wn = wid & 3;   // 2x4 warp grid: 64 rows x 32 cols per warp

    const __nv_bfloat16* Ah = g_Xh;
    const __nv_bfloat16* Al = g_Xl;
    const __nv_bfloat16* Bh = g_Wh + (size_t)mat * 1048576;
    const __nv_bfloat16* Bl = g_Wl + (size_t)mat * 1048576;
    uint32_t sAh_b = smem_u32(sAh), sAl_b = smem_u32(sAl);
    uint32_t sBh_b = smem_u32(sBh), sBl_b = smem_u32(sBl);

    float C[4][4][4] = {};
    int lm = lane & 15;

    for (int kc = 0; kc < 32; kc++) {
        __syncthreads();
        #pragma unroll
        for (int i = tid; i < 512; i += 256) {
            int r = i >> 2, c8 = i & 3;
            size_t ga = (size_t)(stile * 128 + r) * 1024 + kc * 32 + c8 * 8;
            size_t gb = (size_t)(octile * 128 + r) * 1024 + kc * 32 + c8 * 8;
            int so = r * PAD + c8 * 8;
            *(uint4*)&sAh[so] = *(const uint4*)&Ah[ga];
            *(uint4*)&sAl[so] = *(const uint4*)&Al[ga];
            *(uint4*)&sBh[so] = *(const uint4*)&Bh[gb];
            *(uint4*)&sBl[so] = *(const uint4*)&Bl[gb];
        }
        __syncthreads();
        #pragma unroll
        for (int ks = 0; ks < 2; ks++) {
            uint32_t ah[4][4], al[4][4];
            #pragma unroll
            for (int mt = 0; mt < 4; mt++) {
                uint32_t off = ((uint32_t)(wm * 64 + mt * 16 + lm) * PAD
                                + ks * 16 + ((lane >> 4) << 3)) * 2;
                ldsm_x4(sAh_b + off, ah[mt][0], ah[mt][1], ah[mt][2], ah[mt][3]);
                ldsm_x4(sAl_b + off, al[mt][0], al[mt][1], al[mt][2], al[mt][3]);
            }
            #pragma unroll
            for (int nt = 0; nt < 4; nt++) {
                uint32_t off = ((uint32_t)(wn * 32 + nt * 8 + (lm & 7)) * PAD
                                + ks * 16 + ((lm >> 3) << 3)) * 2;
                uint32_t bh0, bh1, bl0, bl1;
                ldsm_x2(sBh_b + off, bh0, bh1);
                ldsm_x2(sBl_b + off, bl0, bl1);
                #pragma unroll
                for (int mt = 0; mt < 4; mt++) {
                    mma16816(C[mt][nt], ah[mt][0], ah[mt][1], ah[mt][2], ah[mt][3], bh0, bh1);
                    mma16816(C[mt][nt], ah[mt][0], ah[mt][1], ah[mt][2], ah[mt][3], bl0, bl1);
                    mma16816(C[mt][nt], al[mt][0], al[mt][1], al[mt][2], al[mt][3], bh0, bh1);
                }
            }
        }
    }

    // epilogue: bias, scale (Q only), split, store [bh][s][64]
    const float* bias = (mat == 0 ? bq : (mat == 1 ? bk : bv));
    float scale = (mat == 0) ? 0.125f : 1.0f;
    __nv_bfloat16* Dh = (mat == 0 ? g_Qh : (mat == 1 ? g_Kh : g_Vh));
    __nv_bfloat16* Dl = (mat == 0 ? g_Ql : (mat == 1 ? g_Kl : g_Vl));
    #pragma unroll
    for (int mt = 0; mt < 4; mt++) {
        #pragma unroll
        for (int nt = 0; nt < 4; nt++) {
            int col = octile * 128 + wn * 32 + nt * 8 + 2 * (lane & 3);
            float b0 = __ldg(bias + col), b1 = __ldg(bias + col + 1);
            int hh = col >> 6, e = col & 63;
            #pragma unroll
            for (int hf = 0; hf < 2; hf++) {
                int row = stile * 128 + wm * 64 + mt * 16 + (lane >> 2) + 8 * hf;
                float v0 = (C[mt][nt][2 * hf + 0] + b0) * scale;
                float v1 = (C[mt][nt][2 * hf + 1] + b1) * scale;
                uint32_t hw, lw;
                split2(v0, v1, hw, lw);
                int b = row >> 11, s = row & 2047;
                size_t o = ((size_t)(b * 16 + hh) * 2048 + s) * 64 + e;
                *(uint32_t*)&Dh[o] = hw;
                *(uint32_t*)&Dl[o] = lw;
            }
        }
    }
}

// ---------------- attention: full-row softmax + post-softmax tril ----------------
#define QP 72
#define SQH 0
#define SQL 9216
#define SKH 18432
#define SKL 27648
#define SVH 36864
#define SVL 46080
#define A_SMEM (55296 * 2)

__global__ __launch_bounds__(256) void attn(float* __restrict__ out) {
    extern __shared__ __align__(16) __nv_bfloat16 sm[];
    __shared__ float s_lsum[128];
    int tid = threadIdx.x, lane = tid & 31, wid = tid >> 5;
    int qt = blockIdx.x, bh = blockIdx.y;
    int b = bh >> 4, h = bh & 15;
    int wm = wid >> 1, wn = wid & 1;   // 4x2: 32 rows x 64 cols per warp
    int lm = lane & 15;

    uint32_t base = smem_u32(sm);
    const __nv_bfloat16* Qh = g_Qh + ((size_t)bh * 2048 + qt * 128) * 64;
    const __nv_bfloat16* Ql = g_Ql + ((size_t)bh * 2048 + qt * 128) * 64;
    #pragma unroll
    for (int i = tid; i < 1024; i += 256) {
        int r = i >> 3, c8 = i & 7;
        *(uint4*)&sm[SQH + r * QP + c8 * 8] = *(const uint4*)&Qh[r * 64 + c8 * 8];
        *(uint4*)&sm[SQL + r * QP + c8 * 8] = *(const uint4*)&Ql[r * 64 + c8 * 8];
    }
    if (tid < 128) s_lsum[tid] = 0.f;

    float O[2][8][4] = {};
    float lsum[2][2] = {};

    for (int kt = 0; kt < 16; kt++) {
        __syncthreads();
        const __nv_bfloat16* Kh = g_Kh + ((size_t)bh * 2048 + kt * 128) * 64;
        const __nv_bfloat16* Kl = g_Kl + ((size_t)bh * 2048 + kt * 128) * 64;
        const __nv_bfloat16* Vh = g_Vh + ((size_t)bh * 2048 + kt * 128) * 64;
        const __nv_bfloat16* Vl = g_Vl + ((size_t)bh * 2048 + kt * 128) * 64;
        #pragma unroll
        for (int i = tid; i < 1024; i += 256) {
            int r = i >> 3, c8 = i & 7;
            int so = r * QP + c8 * 8, go = r * 64 + c8 * 8;
            *(uint4*)&sm[SKH + so] = *(const uint4*)&Kh[go];
            *(uint4*)&sm[SKL + so] = *(const uint4*)&Kl[go];
            *(uint4*)&sm[SVH + so] = *(const uint4*)&Vh[go];
            *(uint4*)&sm[SVL + so] = *(const uint4*)&Vl[go];
        }
        __syncthreads();

        // ---- S = Q·K^T (32x128 per warp over its 64-col half... 2m x 8n tiles)
        float S[2][8][4] = {};
        #pragma unroll
        for (int ks = 0; ks < 4; ks++) {
            uint32_t qah[2][4], qal[2][4];
            #pragma unroll
            for (int mt = 0; mt < 2; mt++) {
                uint32_t off = ((uint32_t)(wm * 32 + mt * 16 + lm) * QP
                                + ks * 16 + ((lane >> 4) << 3)) * 2;
                ldsm_x4(base + (SQH * 2) + off, qah[mt][0], qah[mt][1], qah[mt][2], qah[mt][3]);
                ldsm_x4(base + (SQL * 2) + off, qal[mt][0], qal[mt][1], qal[mt][2], qal[mt][3]);
            }
            #pragma unroll
            for (int nt = 0; nt < 8; nt++) {
                uint32_t off = ((uint32_t)(wn * 64 + nt * 8 + (lm & 7)) * QP
                                + ks * 16 + ((lm >> 3) << 3)) * 2;
                uint32_t kh0, kh1, kl0, kl1;
                ldsm_x2(base + (SKH * 2) + off, kh0, kh1);
                ldsm_x2(base + (SKL * 2) + off, kl0, kl1);
                #pragma unroll
                for (int mt = 0; mt < 2; mt++) {
                    mma16816(S[mt][nt], qah[mt][0], qah[mt][1], qah[mt][2], qah[mt][3], kh0, kh1);
                    mma16816(S[mt][nt], qah[mt][0], qah[mt][1], qah[mt][2], qah[mt][3], kl0, kl1);
                    mma16816(S[mt][nt], qal[mt][0], qal[mt][1], qal[mt][2], qal[mt][3], kh0, kh1);
                }
            }
        }

        // ---- exp + full-row denominator + post-softmax tril mask
        #pragma unroll
        for (int mt = 0; mt < 2; mt++) {
            #pragma unroll
            for (int nt = 0; nt < 8; nt++) {
                int colg = kt * 128 + wn * 64 + nt * 8 + 2 * (lane & 3);
                #pragma unroll
                for (int hf = 0; hf < 2; hf++) {
                    int rg = qt * 128 + wm * 32 + mt * 16 + (lane >> 2) + 8 * hf;
                    float e0 = fast_exp(S[mt][nt][2 * hf + 0]);
                    float e1 = fast_exp(S[mt][nt][2 * hf + 1]);
                    lsum[mt][hf] += e0 + e1;
                    S[mt][nt][2 * hf + 0] = (colg     <= rg) ? e0 : 0.f;
                    S[mt][nt][2 * hf + 1] = (colg + 1 <= rg) ? e1 : 0.f;
                }
            }
        }

        // ---- PV over this warp's 64-col k-slice (skip fully masked tiles)
        if (kt <= qt) {
            uint32_t pah[2][4][4], pal[2][4][4];
            #pragma unroll
            for (int mt = 0; mt < 2; mt++)
                #pragma unroll
                for (int k2 = 0; k2 < 4; k2++) {
                    split2(S[mt][2*k2  ][0], S[mt][2*k2  ][1], pah[mt][k2][0], pal[mt][k2][0]);
                    split2(S[mt][2*k2  ][2], S[mt][2*k2  ][3], pah[mt][k2][1], pal[mt][k2][1]);
                    split2(S[mt][2*k2+1][0], S[mt][2*k2+1][1], pah[mt][k2][2], pal[mt][k2][2]);
                    split2(S[mt][2*k2+1][2], S[mt][2*k2+1][3], pah[mt][k2][3], pal[mt][k2][3]);
                }
            #pragma unroll
            for (int k2 = 0; k2 < 4; k2++) {
                int t0 = wn * 64 + k2 * 16;
                #pragma unroll
                for (int nt = 0; nt < 8; nt++) {
                    uint32_t off = ((uint32_t)(t0 + lm) * QP + nt * 8) * 2;
                    uint32_t vh0, vh1, vl0, vl1;
                    ldsm_x2t(base + (SVH * 2) + off, vh0, vh1);
                    ldsm_x2t(base + (SVL * 2) + off, vl0, vl1);
                    #pragma unroll
                    for (int mt = 0; mt < 2; mt++) {
                        mma16816(O[mt][nt], pah[mt][k2][0], pah[mt][k2][1],
                                 pah[mt][k2][2], pah[mt][k2][3], vh0, vh1);
                        mma16816(O[mt][nt], pah[mt][k2][0], pah[mt][k2][1],
                                 pah[mt][k2][2], pah[mt][k2][3], vl0, vl1);
                        mma16816(O[mt][nt], pal[mt][k2][0], pal[mt][k2][1],
                                 pal[mt][k2][2], pal[mt][k2][3], vh0, vh1);
                    }
                }
            }
        }
    }

    // ---- denominator reduction (quad shfl + cross-warp atomic)
    #pragma unroll
    for (int mt = 0; mt < 2; mt++)
        #pragma unroll
        for (int hf = 0; hf < 2; hf++) {
            float v = lsum[mt][hf];
            v += __shfl_xor_sync(0xffffffffu, v, 1);
            v += __shfl_xor_sync(0xffffffffu, v, 2);
            if ((lane & 3) == 0)
                atomicAdd(&s_lsum[wm * 32 + mt * 16 + (lane >> 2) + 8 * hf], v);
        }
    __syncthreads();

    // ---- O reduction across the 2 n-warps (k-slices), divide, write out
    float* stage = (float*)sm;   // reuses sQ/sK region (dead); 32KB
    if (wn == 1) {
        #pragma unroll
        for (int mt = 0; mt < 2; mt++)
            #pragma unroll
            for (int nt = 0; nt < 8; nt++)
                #pragma unroll
                for (int hf = 0; hf < 2; hf++) {
                    int r = wm * 32 + mt * 16 + (lane >> 2) + 8 * hf;
                    int c = nt * 8 + 2 * (lane & 3);
                    stage[r * 64 + c]     = O[mt][nt][2 * hf + 0];
                    stage[r * 64 + c + 1] = O[mt][nt][2 * hf + 1];
                }
    }
    __syncthreads();
    if (wn == 0) {
        #pragma unroll
        for (int mt = 0; mt < 2; mt++)
            #pragma unroll
            for (int hf = 0; hf < 2; hf++) {
                int r = wm * 32 + mt * 16 + (lane >> 2) + 8 * hf;
                float inv = 1.0f / s_lsum[r];
                float* ob = out + ((size_t)b * 2048 + qt * 128 + r) * 1024 + h * 64;
                #pragma unroll
                for (int nt = 0; nt < 8; nt++) {
                    int c = nt * 8 + 2 * (lane & 3);
                    float o0 = (O[mt][nt][2 * hf + 0] + stage[r * 64 + c])     * inv;
                    float o1 = (O[mt][nt][2 * hf + 1] + stage[r * 64 + c + 1]) * inv;
                    *(float2*)&ob[c] = make_float2(o0, o1);
                }
            }
    }
}

extern "C" void kernel_launch(void* const* d_in, const int* in_sizes, int n_in,
                              void* d_out, int out_size) {
    const float* X  = (const float*)d_in[0];
    const float* Wq = (const float*)d_in[1];
    const float* bq = (const float*)d_in[2];
    const float* Wk = (const float*)d_in[3];
    const float* bk = (const float*)d_in[4];
    const float* Wv = (const float*)d_in[5];
    const float* bv = (const float*)d_in[6];

    cudaFuncSetAttribute(attn, cudaFuncAttributeMaxDynamicSharedMemorySize, A_SMEM);

    prep_x<<<4096, 256>>>(X);
    prep_w<<<dim3(32, 2, 48), dim3(32, 8)>>>(Wq, Wk, Wv);
    qkv_mm<<<dim3(32, 8, 3), 256>>>(bq, bk, bv);
    attn<<<dim3(16, 32), 256, A_SMEM>>>((float*)d_out);
}

// round 5
// speedup vs baseline: 2.5844x; 1.1673x over previous
#include <cuda_runtime.h>
#include <cuda_bf16.h>
#include <cstdint>

// ---------------- scratch (device globals) ----------------
__device__ __align__(16) __nv_bfloat16 g_Xh[4096*1024], g_Xl[4096*1024];
__device__ __align__(16) __nv_bfloat16 g_Wh[3*1024*1024], g_Wl[3*1024*1024];
__device__ __align__(16) __nv_bfloat16 g_Qh[32*2048*64], g_Ql[32*2048*64];
__device__ __align__(16) __nv_bfloat16 g_Kh[32*2048*64], g_Kl[32*2048*64];
__device__ __align__(16) __nv_bfloat16 g_Vh[32*2048*64], g_Vl[32*2048*64];

// ---------------- helpers ----------------
__device__ __forceinline__ uint32_t smem_u32(const void* p) {
    uint32_t a;
    asm("{ .reg .u64 t; cvta.to.shared.u64 t, %1; cvt.u32.u64 %0, t; }" : "=r"(a) : "l"(p));
    return a;
}
__device__ __forceinline__ uint32_t packbf(__nv_bfloat16 a, __nv_bfloat16 b) {
    return (uint32_t)*(uint16_t*)&a | ((uint32_t)*(uint16_t*)&b << 16);
}
__device__ __forceinline__ void split2(float a, float b, uint32_t& hw, uint32_t& lw) {
    __nv_bfloat16 ha = __float2bfloat16(a), hb = __float2bfloat16(b);
    hw = packbf(ha, hb);
    lw = packbf(__float2bfloat16(a - __bfloat162float(ha)),
                __float2bfloat16(b - __bfloat162float(hb)));
}
__device__ __forceinline__ float fast_exp(float x) {
    float y = fmaxf(x * 1.4426950408889634f, -100.0f);
    float z = y + 12582912.0f;
    int   n = __float_as_int(z) - 0x4B400000;
    float f = y - (z - 12582912.0f);
    float p = 1.33335581e-3f;
    p = fmaf(p, f, 9.61812911e-3f);
    p = fmaf(p, f, 5.55041087e-2f);
    p = fmaf(p, f, 2.40226507e-1f);
    p = fmaf(p, f, 6.93147181e-1f);
    p = fmaf(p, f, 1.0f);
    return __int_as_float(__float_as_int(p) + (n << 23));
}
__device__ __forceinline__ void ldsm_x4(uint32_t a, uint32_t& r0, uint32_t& r1,
                                        uint32_t& r2, uint32_t& r3) {
    asm volatile("ldmatrix.sync.aligned.m8n8.x4.shared.b16 {%0,%1,%2,%3}, [%4];"
        : "=r"(r0), "=r"(r1), "=r"(r2), "=r"(r3) : "r"(a));
}
__device__ __forceinline__ void ldsm_x4t(uint32_t a, uint32_t& r0, uint32_t& r1,
                                         uint32_t& r2, uint32_t& r3) {
    asm volatile("ldmatrix.sync.aligned.m8n8.x4.trans.shared.b16 {%0,%1,%2,%3}, [%4];"
        : "=r"(r0), "=r"(r1), "=r"(r2), "=r"(r3) : "r"(a));
}
__device__ __forceinline__ void mma16816(float* c, const uint32_t* a,
                                         uint32_t b0, uint32_t b1) {
    asm volatile("mma.sync.aligned.m16n8k16.row.col.f32.bf16.bf16.f32 "
        "{%0,%1,%2,%3}, {%4,%5,%6,%7}, {%8,%9}, {%0,%1,%2,%3};"
        : "+f"(c[0]), "+f"(c[1]), "+f"(c[2]), "+f"(c[3])
        : "r"(a[0]), "r"(a[1]), "r"(a[2]), "r"(a[3]), "r"(b0), "r"(b1));
}
__device__ __forceinline__ void cpa16(uint32_t dst, const void* src) {
    asm volatile("cp.async.cg.shared.global [%0], [%1], 16;" :: "r"(dst), "l"(src));
}
__device__ __forceinline__ void cpcommit() { asm volatile("cp.async.commit_group;"); }
__device__ __forceinline__ void cpwait1()  { asm volatile("cp.async.wait_group 1;"); }
__device__ __forceinline__ void cpwait0()  { asm volatile("cp.async.wait_group 0;"); }

// ---------------- prep: split X ----------------
__global__ __launch_bounds__(256) void prep_x(const float* __restrict__ X) {
    size_t i = (size_t)blockIdx.x * 256 + threadIdx.x;
    float4 v = ((const float4*)X)[i];
    uint32_t h0, l0, h1, l1;
    split2(v.x, v.y, h0, l0);
    split2(v.z, v.w, h1, l1);
    ((uint2*)g_Xh)[i] = make_uint2(h0, h1);
    ((uint2*)g_Xl)[i] = make_uint2(l0, l1);
}

// ---------------- prep: transpose+split W -> [mat][h*64+e][d] ----------------
__global__ __launch_bounds__(256) void prep_w(const float* __restrict__ Wq,
                                              const float* __restrict__ Wk,
                                              const float* __restrict__ Wv) {
    int z = blockIdx.z, mat = z >> 4, h = z & 15;
    const float* W = (mat == 0 ? Wq : (mat == 1 ? Wk : Wv)) + (size_t)h * 1024 * 64;
    __shared__ float t[32][33];
    int d0 = blockIdx.x * 32, e0 = blockIdx.y * 32;
    int tx = threadIdx.x, ty = threadIdx.y;
    #pragma unroll
    for (int k = 0; k < 4; k++)
        t[ty + 8 * k][tx] = W[(size_t)(d0 + ty + 8 * k) * 64 + e0 + tx];
    __syncthreads();
    __nv_bfloat16* oh = g_Wh + (size_t)mat * 1048576;
    __nv_bfloat16* ol = g_Wl + (size_t)mat * 1048576;
    #pragma unroll
    for (int k = 0; k < 4; k++) {
        int j = ty + 8 * k;
        float v = t[tx][j];
        __nv_bfloat16 hv = __float2bfloat16(v);
        size_t o = (size_t)(h * 64 + e0 + j) * 1024 + d0 + tx;
        oh[o] = hv;
        ol[o] = __float2bfloat16(v - __bfloat162float(hv));
    }
}

// ---------------- QKV GEMM: 128x64 CTA tile, cp.async double buffer ----------------
#define GP 40
// dyn smem (bf16 elems): per stage 15360: Ah 0(5120) Al 5120 Bh 10240(2560) Bl 12800
#define QKV_SMEM (2 * 15360 * 2)

__device__ __forceinline__ void qkv_prefetch(uint32_t sb, int st, int stile, int octile,
                                             int kc, int tid,
                                             const __nv_bfloat16* Bh,
                                             const __nv_bfloat16* Bl) {
    uint32_t s0 = sb + st * 15360 * 2;
    #pragma unroll
    for (int i = tid; i < 512; i += 256) {
        int r = i >> 2, c8 = i & 3;
        uint32_t d = s0 + (r * GP + c8 * 8) * 2;
        size_t g = (size_t)(stile * 128 + r) * 1024 + kc * 32 + c8 * 8;
        cpa16(d, g_Xh + g);
        cpa16(d + 5120 * 2, g_Xl + g);
    }
    {
        int i = tid;   // 256 chunks
        int r = i >> 2, c8 = i & 3;
        uint32_t d = s0 + (10240 + r * GP + c8 * 8) * 2;
        size_t g = (size_t)(octile * 64 + r) * 1024 + kc * 32 + c8 * 8;
        cpa16(d, Bh + g);
        cpa16(d + 2560 * 2, Bl + g);
    }
}

__global__ __launch_bounds__(256, 2) void qkv_mm(const float* __restrict__ bq,
                                                 const float* __restrict__ bk,
                                                 const float* __restrict__ bv) {
    extern __shared__ __align__(16) __nv_bfloat16 smq[];
    uint32_t sb = smem_u32(smq);
    int tid = threadIdx.x, lane = tid & 31, wid = tid >> 5;
    int stile = blockIdx.x, octile = blockIdx.y, mat = blockIdx.z;
    int wm = wid >> 1, wn = wid & 1;   // 4x2: warp = 32 rows x 32 cols
    int lm = lane & 15;

    const __nv_bfloat16* Bh = g_Wh + (size_t)mat * 1048576;
    const __nv_bfloat16* Bl = g_Wl + (size_t)mat * 1048576;

    float C[2][4][4] = {};

    qkv_prefetch(sb, 0, stile, octile, 0, tid, Bh, Bl);
    cpcommit();

    for (int kc = 0; kc < 32; kc++) {
        if (kc < 31) {
            qkv_prefetch(sb, (kc + 1) & 1, stile, octile, kc + 1, tid, Bh, Bl);
            cpcommit();
            cpwait1();
        } else {
            cpwait0();
        }
        __syncthreads();
        uint32_t bufA = sb + (kc & 1) * 15360 * 2;
        uint32_t bufBh = bufA + 10240 * 2, bufBl = bufA + 12800 * 2;
        #pragma unroll
        for (int ks = 0; ks < 2; ks++) {
            uint32_t ah[2][4], al[2][4];
            #pragma unroll
            for (int mt = 0; mt < 2; mt++) {
                uint32_t off = ((uint32_t)(wm * 32 + mt * 16 + lm) * GP
                                + ks * 16 + ((lane >> 4) << 3)) * 2;
                ldsm_x4(bufA + off, ah[mt][0], ah[mt][1], ah[mt][2], ah[mt][3]);
                ldsm_x4(bufA + 5120 * 2 + off, al[mt][0], al[mt][1], al[mt][2], al[mt][3]);
            }
            #pragma unroll
            for (int ntp = 0; ntp < 2; ntp++) {
                uint32_t off = ((uint32_t)(wn * 32 + ntp * 16 + ((lane >> 4) << 3) + (lane & 7)) * GP
                                + ks * 16 + (((lane >> 3) & 1) << 3)) * 2;
                uint32_t h0, h1, h2, h3, l0, l1, l2, l3;
                ldsm_x4(bufBh + off, h0, h1, h2, h3);
                ldsm_x4(bufBl + off, l0, l1, l2, l3);
                #pragma unroll
                for (int mt = 0; mt < 2; mt++) {
                    mma16816(C[mt][2 * ntp],     ah[mt], h0, h1);
                    mma16816(C[mt][2 * ntp],     ah[mt], l0, l1);
                    mma16816(C[mt][2 * ntp],     al[mt], h0, h1);
                    mma16816(C[mt][2 * ntp + 1], ah[mt], h2, h3);
                    mma16816(C[mt][2 * ntp + 1], ah[mt], l2, l3);
                    mma16816(C[mt][2 * ntp + 1], al[mt], h2, h3);
                }
            }
        }
        __syncthreads();
    }

    const float* bias = (mat == 0 ? bq : (mat == 1 ? bk : bv));
    float scale = (mat == 0) ? 0.125f : 1.0f;
    __nv_bfloat16* Dh = (mat == 0 ? g_Qh : (mat == 1 ? g_Kh : g_Vh));
    __nv_bfloat16* Dl = (mat == 0 ? g_Ql : (mat == 1 ? g_Kl : g_Vl));
    #pragma unroll
    for (int mt = 0; mt < 2; mt++) {
        #pragma unroll
        for (int nt = 0; nt < 4; nt++) {
            int col = octile * 64 + wn * 32 + nt * 8 + 2 * (lane & 3);
            float b0 = __ldg(bias + col), b1 = __ldg(bias + col + 1);
            int hh = col >> 6, e = col & 63;
            #pragma unroll
            for (int hf = 0; hf < 2; hf++) {
                int row = stile * 128 + wm * 32 + mt * 16 + (lane >> 2) + 8 * hf;
                float v0 = (C[mt][nt][2 * hf + 0] + b0) * scale;
                float v1 = (C[mt][nt][2 * hf + 1] + b1) * scale;
                uint32_t hw, lw;
                split2(v0, v1, hw, lw);
                int b = row >> 11, s = row & 2047;
                size_t o = ((size_t)(b * 16 + hh) * 2048 + s) * 64 + e;
                *(uint32_t*)&Dh[o] = hw;
                *(uint32_t*)&Dl[o] = lw;
            }
        }
    }
}

// ---------------- attention: 8x1 warps, 2 CTAs/SM ----------------
#define QP 72
#define SQH 0
#define SQL 9216
#define SKH 18432
#define SKL 27648
#define SVH 36864
#define SVL 46080
#define A_SMEM (55296 * 2)

__global__ __launch_bounds__(256, 2) void attn(float* __restrict__ out) {
    extern __shared__ __align__(16) __nv_bfloat16 sm[];
    int tid = threadIdx.x, lane = tid & 31, w = tid >> 5;
    int bh = blockIdx.x >> 4, qt = 15 - (blockIdx.x & 15);   // heavy-first
    int b = bh >> 4, h = bh & 15;
    int lm = lane & 15;
    uint32_t base = smem_u32(sm);

    // cooperative Q load (128x64 h/l)
    const __nv_bfloat16* Qh = g_Qh + ((size_t)bh * 2048 + qt * 128) * 64;
    const __nv_bfloat16* Ql = g_Ql + ((size_t)bh * 2048 + qt * 128) * 64;
    #pragma unroll
    for (int i = tid; i < 1024; i += 256) {
        int r = i >> 3, c8 = i & 7;
        *(uint4*)&sm[SQH + r * QP + c8 * 8] = *(const uint4*)&Qh[r * 64 + c8 * 8];
        *(uint4*)&sm[SQL + r * QP + c8 * 8] = *(const uint4*)&Ql[r * 64 + c8 * 8];
    }
    __syncthreads();

    // Q fragments resident for the whole kernel (warp's 16 rows)
    uint32_t qh[4][4], ql[4][4];
    #pragma unroll
    for (int ks = 0; ks < 4; ks++) {
        uint32_t off = ((uint32_t)(w * 16 + lm) * QP + ks * 16 + ((lane >> 4) << 3)) * 2;
        ldsm_x4(base + SQH * 2 + off, qh[ks][0], qh[ks][1], qh[ks][2], qh[ks][3]);
        ldsm_x4(base + SQL * 2 + off, ql[ks][0], ql[ks][1], ql[ks][2], ql[ks][3]);
    }

    float O[8][4] = {};
    float lsum[2] = {};
    int rbase = qt * 128 + w * 16 + (lane >> 2);

    for (int kt = 0; kt < 16; kt++) {
        __syncthreads();
        const __nv_bfloat16* Kh = g_Kh + ((size_t)bh * 2048 + kt * 128) * 64;
        const __nv_bfloat16* Kl = g_Kl + ((size_t)bh * 2048 + kt * 128) * 64;
        const __nv_bfloat16* Vh = g_Vh + ((size_t)bh * 2048 + kt * 128) * 64;
        const __nv_bfloat16* Vl = g_Vl + ((size_t)bh * 2048 + kt * 128) * 64;
        #pragma unroll
        for (int i = tid; i < 1024; i += 256) {
            int r = i >> 3, c8 = i & 7;
            int so = r * QP + c8 * 8, go = r * 64 + c8 * 8;
            *(uint4*)&sm[SKH + so] = *(const uint4*)&Kh[go];
            *(uint4*)&sm[SKL + so] = *(const uint4*)&Kl[go];
            *(uint4*)&sm[SVH + so] = *(const uint4*)&Vh[go];
            *(uint4*)&sm[SVL + so] = *(const uint4*)&Vl[go];
        }
        __syncthreads();

        bool live = (kt <= qt);
        int cb = kt * 128 + 2 * (lane & 3);

        #pragma unroll
        for (int k2 = 0; k2 < 8; k2++) {
            // ---- S slice: 16 rows x 16 cols (nt = 2k2, 2k2+1)
            float S[2][4] = {};
            #pragma unroll
            for (int ks = 0; ks < 4; ks++) {
                uint32_t off = ((uint32_t)(k2 * 16 + ((lane >> 4) << 3) + (lane & 7)) * QP
                                + ks * 16 + (((lane >> 3) & 1) << 3)) * 2;
                uint32_t h0, h1, h2, h3, l0, l1, l2, l3;
                ldsm_x4(base + SKH * 2 + off, h0, h1, h2, h3);
                ldsm_x4(base + SKL * 2 + off, l0, l1, l2, l3);
                mma16816(S[0], qh[ks], h0, h1);
                mma16816(S[0], qh[ks], l0, l1);
                mma16816(S[0], ql[ks], h0, h1);
                mma16816(S[1], qh[ks], h2, h3);
                mma16816(S[1], qh[ks], l2, l3);
                mma16816(S[1], ql[ks], h2, h3);
            }
            // ---- exp + full-row lsum + post-softmax tril mask
            #pragma unroll
            for (int ntl = 0; ntl < 2; ntl++) {
                int colg = cb + k2 * 16 + ntl * 8;
                #pragma unroll
                for (int hf = 0; hf < 2; hf++) {
                    int rg = rbase + 8 * hf;
                    float e0 = fast_exp(S[ntl][2 * hf + 0]);
                    float e1 = fast_exp(S[ntl][2 * hf + 1]);
                    lsum[hf] += e0 + e1;
                    S[ntl][2 * hf + 0] = (colg     <= rg) ? e0 : 0.f;
                    S[ntl][2 * hf + 1] = (colg + 1 <= rg) ? e1 : 0.f;
                }
            }
            // ---- PV for this 16-wide k-slice
            if (live) {
                uint32_t pah[4], pal[4];
                split2(S[0][0], S[0][1], pah[0], pal[0]);
                split2(S[0][2], S[0][3], pah[1], pal[1]);
                split2(S[1][0], S[1][1], pah[2], pal[2]);
                split2(S[1][2], S[1][3], pah[3], pal[3]);
                #pragma unroll
                for (int ntp = 0; ntp < 4; ntp++) {
                    uint32_t off = ((uint32_t)(k2 * 16 + lm) * QP
                                    + ntp * 16 + ((lane >> 4) << 3)) * 2;
                    uint32_t v0, v1, v2, v3, u0, u1, u2, u3;
                    ldsm_x4t(base + SVH * 2 + off, v0, v1, v2, v3);
                    ldsm_x4t(base + SVL * 2 + off, u0, u1, u2, u3);
                    mma16816(O[2 * ntp],     pah, v0, v1);
                    mma16816(O[2 * ntp],     pah, u0, u1);
                    mma16816(O[2 * ntp],     pal, v0, v1);
                    mma16816(O[2 * ntp + 1], pah, v2, v3);
                    mma16816(O[2 * ntp + 1], pah, u2, u3);
                    mma16816(O[2 * ntp + 1], pal, v2, v3);
                }
            }
        }
    }

    // ---- row denominators: quad butterfly (warp-local rows)
    #pragma unroll
    for (int hf = 0; hf < 2; hf++) {
        lsum[hf] += __shfl_xor_sync(0xffffffffu, lsum[hf], 1);
        lsum[hf] += __shfl_xor_sync(0xffffffffu, lsum[hf], 2);
    }

    // ---- write out (no cross-warp reduction needed)
    #pragma unroll
    for (int hf = 0; hf < 2; hf++) {
        float inv = 1.0f / lsum[hf];
        int rg = rbase + 8 * hf;   // global q row
        float* ob = out + ((size_t)b * 2048 + rg) * 1024 + h * 64;
        #pragma unroll
        for (int nt = 0; nt < 8; nt++) {
            int c = nt * 8 + 2 * (lane & 3);
            *(float2*)&ob[c] = make_float2(O[nt][2 * hf] * inv, O[nt][2 * hf + 1] * inv);
        }
    }
}

extern "C" void kernel_launch(void* const* d_in, const int* in_sizes, int n_in,
                              void* d_out, int out_size) {
    const float* X  = (const float*)d_in[0];
    const float* Wq = (const float*)d_in[1];
    const float* bq = (const float*)d_in[2];
    const float* Wk = (const float*)d_in[3];
    const float* bk = (const float*)d_in[4];
    const float* Wv = (const float*)d_in[5];
    const float* bv = (const float*)d_in[6];

    cudaFuncSetAttribute(qkv_mm, cudaFuncAttributeMaxDynamicSharedMemorySize, QKV_SMEM);
    cudaFuncSetAttribute(attn,   cudaFuncAttributeMaxDynamicSharedMemorySize, A_SMEM);

    prep_x<<<4096, 256>>>(X);
    prep_w<<<dim3(32, 2, 48), dim3(32, 8)>>>(Wq, Wk, Wv);
    qkv_mm<<<dim3(32, 16, 3), 256, QKV_SMEM>>>(bq, bk, bv);
    attn<<<512, 256, A_SMEM>>>((float*)d_out);
}

// round 6
// speedup vs baseline: 2.6073x; 1.0089x over previous
#include <cuda_runtime.h>
#include <cuda_bf16.h>
#include <cstdint>

// ---------------- scratch (device globals) ----------------
__device__ __align__(16) __nv_bfloat16 g_Xh[4096*1024], g_Xl[4096*1024];
__device__ __align__(16) __nv_bfloat16 g_Wh[3*1024*1024], g_Wl[3*1024*1024];
__device__ __align__(16) __nv_bfloat16 g_Qh[32*2048*64], g_Ql[32*2048*64];
__device__ __align__(16) __nv_bfloat16 g_Kh[32*2048*64], g_Kl[32*2048*64];
__device__ __align__(16) __nv_bfloat16 g_Vh[32*2048*64], g_Vl[32*2048*64];

// ---------------- helpers ----------------
__device__ __forceinline__ uint32_t smem_u32(const void* p) {
    uint32_t a;
    asm("{ .reg .u64 t; cvta.to.shared.u64 t, %1; cvt.u32.u64 %0, t; }" : "=r"(a) : "l"(p));
    return a;
}
__device__ __forceinline__ uint32_t packbf(__nv_bfloat16 a, __nv_bfloat16 b) {
    return (uint32_t)*(uint16_t*)&a | ((uint32_t)*(uint16_t*)&b << 16);
}
__device__ __forceinline__ void split2(float a, float b, uint32_t& hw, uint32_t& lw) {
    __nv_bfloat16 ha = __float2bfloat16(a), hb = __float2bfloat16(b);
    hw = packbf(ha, hb);
    lw = packbf(__float2bfloat16(a - __bfloat162float(ha)),
                __float2bfloat16(b - __bfloat162float(hb)));
}
__device__ __forceinline__ float fast_exp(float x) {
    float y = fmaxf(x * 1.4426950408889634f, -100.0f);
    float z = y + 12582912.0f;
    int   n = __float_as_int(z) - 0x4B400000;
    float f = y - (z - 12582912.0f);
    float p = 1.33335581e-3f;
    p = fmaf(p, f, 9.61812911e-3f);
    p = fmaf(p, f, 5.55041087e-2f);
    p = fmaf(p, f, 2.40226507e-1f);
    p = fmaf(p, f, 6.93147181e-1f);
    p = fmaf(p, f, 1.0f);
    return __int_as_float(__float_as_int(p) + (n << 23));
}
__device__ __forceinline__ void ldsm_x4(uint32_t a, uint32_t& r0, uint32_t& r1,
                                        uint32_t& r2, uint32_t& r3) {
    asm volatile("ldmatrix.sync.aligned.m8n8.x4.shared.b16 {%0,%1,%2,%3}, [%4];"
        : "=r"(r0), "=r"(r1), "=r"(r2), "=r"(r3) : "r"(a));
}
__device__ __forceinline__ void ldsm_x4t(uint32_t a, uint32_t& r0, uint32_t& r1,
                                         uint32_t& r2, uint32_t& r3) {
    asm volatile("ldmatrix.sync.aligned.m8n8.x4.trans.shared.b16 {%0,%1,%2,%3}, [%4];"
        : "=r"(r0), "=r"(r1), "=r"(r2), "=r"(r3) : "r"(a));
}
__device__ __forceinline__ void mma16816(float* c, const uint32_t* a,
                                         uint32_t b0, uint32_t b1) {
    asm volatile("mma.sync.aligned.m16n8k16.row.col.f32.bf16.bf16.f32 "
        "{%0,%1,%2,%3}, {%4,%5,%6,%7}, {%8,%9}, {%0,%1,%2,%3};"
        : "+f"(c[0]), "+f"(c[1]), "+f"(c[2]), "+f"(c[3])
        : "r"(a[0]), "r"(a[1]), "r"(a[2]), "r"(a[3]), "r"(b0), "r"(b1));
}
__device__ __forceinline__ void cpa16(uint32_t dst, const void* src) {
    asm volatile("cp.async.cg.shared.global [%0], [%1], 16;" :: "r"(dst), "l"(src));
}
__device__ __forceinline__ void cpcommit() { asm volatile("cp.async.commit_group;"); }
__device__ __forceinline__ void cpwait1()  { asm volatile("cp.async.wait_group 1;"); }
__device__ __forceinline__ void cpwait0()  { asm volatile("cp.async.wait_group 0;"); }

// ---------------- prep: split X ----------------
__global__ __launch_bounds__(256) void prep_x(const float* __restrict__ X) {
    size_t i = (size_t)blockIdx.x * 256 + threadIdx.x;
    float4 v = ((const float4*)X)[i];
    uint32_t h0, l0, h1, l1;
    split2(v.x, v.y, h0, l0);
    split2(v.z, v.w, h1, l1);
    ((uint2*)g_Xh)[i] = make_uint2(h0, h1);
    ((uint2*)g_Xl)[i] = make_uint2(l0, l1);
}

// ---------------- prep: transpose+split W -> [mat][h*64+e][d] ----------------
__global__ __launch_bounds__(256) void prep_w(const float* __restrict__ Wq,
                                              const float* __restrict__ Wk,
                                              const float* __restrict__ Wv) {
    int z = blockIdx.z, mat = z >> 4, h = z & 15;
    const float* W = (mat == 0 ? Wq : (mat == 1 ? Wk : Wv)) + (size_t)h * 1024 * 64;
    __shared__ float t[32][33];
    int d0 = blockIdx.x * 32, e0 = blockIdx.y * 32;
    int tx = threadIdx.x, ty = threadIdx.y;
    #pragma unroll
    for (int k = 0; k < 4; k++)
        t[ty + 8 * k][tx] = W[(size_t)(d0 + ty + 8 * k) * 64 + e0 + tx];
    __syncthreads();
    __nv_bfloat16* oh = g_Wh + (size_t)mat * 1048576;
    __nv_bfloat16* ol = g_Wl + (size_t)mat * 1048576;
    #pragma unroll
    for (int k = 0; k < 4; k++) {
        int j = ty + 8 * k;
        float v = t[tx][j];
        __nv_bfloat16 hv = __float2bfloat16(v);
        size_t o = (size_t)(h * 64 + e0 + j) * 1024 + d0 + tx;
        oh[o] = hv;
        ol[o] = __float2bfloat16(v - __bfloat162float(hv));
    }
}

// ---------------- QKV GEMM: 128x64 CTA tile, cp.async double buffer ----------------
#define GP 40
#define QKV_SMEM (2 * 15360 * 2)

__device__ __forceinline__ void qkv_prefetch(uint32_t sb, int st, int stile, int octile,
                                             int kc, int tid,
                                             const __nv_bfloat16* Bh,
                                             const __nv_bfloat16* Bl) {
    uint32_t s0 = sb + st * 15360 * 2;
    #pragma unroll
    for (int i = tid; i < 512; i += 256) {
        int r = i >> 2, c8 = i & 3;
        uint32_t d = s0 + (r * GP + c8 * 8) * 2;
        size_t g = (size_t)(stile * 128 + r) * 1024 + kc * 32 + c8 * 8;
        cpa16(d, g_Xh + g);
        cpa16(d + 5120 * 2, g_Xl + g);
    }
    {
        int i = tid;
        int r = i >> 2, c8 = i & 3;
        uint32_t d = s0 + (10240 + r * GP + c8 * 8) * 2;
        size_t g = (size_t)(octile * 64 + r) * 1024 + kc * 32 + c8 * 8;
        cpa16(d, Bh + g);
        cpa16(d + 2560 * 2, Bl + g);
    }
}

__global__ __launch_bounds__(256, 2) void qkv_mm(const float* __restrict__ bq,
                                                 const float* __restrict__ bk,
                                                 const float* __restrict__ bv) {
    extern __shared__ __align__(16) __nv_bfloat16 smq[];
    uint32_t sb = smem_u32(smq);
    int tid = threadIdx.x, lane = tid & 31, wid = tid >> 5;
    int stile = blockIdx.x, octile = blockIdx.y, mat = blockIdx.z;
    int wm = wid >> 1, wn = wid & 1;
    int lm = lane & 15;

    const __nv_bfloat16* Bh = g_Wh + (size_t)mat * 1048576;
    const __nv_bfloat16* Bl = g_Wl + (size_t)mat * 1048576;

    float C[2][4][4] = {};

    qkv_prefetch(sb, 0, stile, octile, 0, tid, Bh, Bl);
    cpcommit();

    for (int kc = 0; kc < 32; kc++) {
        if (kc < 31) {
            qkv_prefetch(sb, (kc + 1) & 1, stile, octile, kc + 1, tid, Bh, Bl);
            cpcommit();
            cpwait1();
        } else {
            cpwait0();
        }
        __syncthreads();
        uint32_t bufA = sb + (kc & 1) * 15360 * 2;
        uint32_t bufBh = bufA + 10240 * 2, bufBl = bufA + 12800 * 2;
        #pragma unroll
        for (int ks = 0; ks < 2; ks++) {
            uint32_t ah[2][4], al[2][4];
            #pragma unroll
            for (int mt = 0; mt < 2; mt++) {
                uint32_t off = ((uint32_t)(wm * 32 + mt * 16 + lm) * GP
                                + ks * 16 + ((lane >> 4) << 3)) * 2;
                ldsm_x4(bufA + off, ah[mt][0], ah[mt][1], ah[mt][2], ah[mt][3]);
                ldsm_x4(bufA + 5120 * 2 + off, al[mt][0], al[mt][1], al[mt][2], al[mt][3]);
            }
            #pragma unroll
            for (int ntp = 0; ntp < 2; ntp++) {
                uint32_t off = ((uint32_t)(wn * 32 + ntp * 16 + ((lane >> 4) << 3) + (lane & 7)) * GP
                                + ks * 16 + (((lane >> 3) & 1) << 3)) * 2;
                uint32_t h0, h1, h2, h3, l0, l1, l2, l3;
                ldsm_x4(bufBh + off, h0, h1, h2, h3);
                ldsm_x4(bufBl + off, l0, l1, l2, l3);
                #pragma unroll
                for (int mt = 0; mt < 2; mt++) {
                    mma16816(C[mt][2 * ntp],     ah[mt], h0, h1);
                    mma16816(C[mt][2 * ntp],     ah[mt], l0, l1);
                    mma16816(C[mt][2 * ntp],     al[mt], h0, h1);
                    mma16816(C[mt][2 * ntp + 1], ah[mt], h2, h3);
                    mma16816(C[mt][2 * ntp + 1], ah[mt], l2, l3);
                    mma16816(C[mt][2 * ntp + 1], al[mt], h2, h3);
                }
            }
        }
        __syncthreads();
    }

    const float* bias = (mat == 0 ? bq : (mat == 1 ? bk : bv));
    float scale = (mat == 0) ? 0.125f : 1.0f;
    __nv_bfloat16* Dh = (mat == 0 ? g_Qh : (mat == 1 ? g_Kh : g_Vh));
    __nv_bfloat16* Dl = (mat == 0 ? g_Ql : (mat == 1 ? g_Kl : g_Vl));
    #pragma unroll
    for (int mt = 0; mt < 2; mt++) {
        #pragma unroll
        for (int nt = 0; nt < 4; nt++) {
            int col = octile * 64 + wn * 32 + nt * 8 + 2 * (lane & 3);
            float b0 = __ldg(bias + col), b1 = __ldg(bias + col + 1);
            int hh = col >> 6, e = col & 63;
            #pragma unroll
            for (int hf = 0; hf < 2; hf++) {
                int row = stile * 128 + wm * 32 + mt * 16 + (lane >> 2) + 8 * hf;
                float v0 = (C[mt][nt][2 * hf + 0] + b0) * scale;
                float v1 = (C[mt][nt][2 * hf + 1] + b1) * scale;
                uint32_t hw, lw;
                split2(v0, v1, hw, lw);
                int b = row >> 11, s = row & 2047;
                size_t o = ((size_t)(b * 16 + hh) * 2048 + s) * 64 + e;
                *(uint32_t*)&Dh[o] = hw;
                *(uint32_t*)&Dl[o] = lw;
            }
        }
    }
}

// ---------------- attention: 512 thr, 256 q-rows, cp.async double-buffered K/V ----------------
#define REG 16384                      // one region: 128 rows x 64 bf16 = 16KB
#define STAGE (4 * REG)                // KH KL VH VL
#define A_SMEM (2 * STAGE)             // 128KB

// swizzled byte offset within a region: row r (0..127), 16B chunk c8 (0..7)
__device__ __forceinline__ uint32_t swoff(int r, int c8) {
    return (uint32_t)(((r << 3) + (c8 ^ (r & 7))) << 4);
}

__device__ __forceinline__ void attn_prefetch(uint32_t sb, int st, int tid,
                                              const __nv_bfloat16* Kh,
                                              const __nv_bfloat16* Kl,
                                              const __nv_bfloat16* Vh,
                                              const __nv_bfloat16* Vl) {
    uint32_t s0 = sb + st * STAGE;
    #pragma unroll
    for (int i = tid; i < 1024; i += 512) {
        int r = i >> 3, c8 = i & 7;
        uint32_t d = swoff(r, c8);
        size_t g = (size_t)r * 64 + c8 * 8;
        cpa16(s0 + d,           Kh + g);
        cpa16(s0 + REG + d,     Kl + g);
        cpa16(s0 + 2 * REG + d, Vh + g);
        cpa16(s0 + 3 * REG + d, Vl + g);
    }
}

__global__ __launch_bounds__(512, 1) void attn(float* __restrict__ out) {
    extern __shared__ __align__(16) char sm[];
    uint32_t sb = smem_u32(sm);
    int tid = threadIdx.x, lane = tid & 31, w = tid >> 5;
    int bh = blockIdx.x >> 3, qt = 7 - (blockIdx.x & 7);   // heavy-first
    int b = bh >> 4, h = bh & 15;
    int lm = lane & 15;

    // ---- stage Q (256x64 h/l) through stage-0 buffer, extract fragments, recycle
    const __nv_bfloat16* Qh = g_Qh + ((size_t)bh * 2048 + qt * 256) * 64;
    const __nv_bfloat16* Ql = g_Ql + ((size_t)bh * 2048 + qt * 256) * 64;
    #pragma unroll
    for (int i = tid; i < 2048; i += 512) {
        int r = i >> 3, c8 = i & 7;
        uint32_t reg0 = (r >= 128) ? REG : 0;
        uint32_t d = reg0 + swoff(r & 127, c8);
        size_t g = (size_t)r * 64 + c8 * 8;
        cpa16(sb + d,           Qh + g);
        cpa16(sb + 2 * REG + d, Ql + g);
    }
    cpcommit(); cpwait0();
    __syncthreads();

    uint32_t qh[4][4], ql[4][4];
    {
        uint32_t qreg = (w >= 8) ? REG : 0;
        int rowb = (w & 7) * 16 + lm;
        #pragma unroll
        for (int ks = 0; ks < 4; ks++) {
            int c8 = ks * 2 + (lane >> 4);
            uint32_t d = swoff(rowb, c8);
            ldsm_x4(sb + qreg + d,           qh[ks][0], qh[ks][1], qh[ks][2], qh[ks][3]);
            ldsm_x4(sb + qreg + 2 * REG + d, ql[ks][0], ql[ks][1], ql[ks][2], ql[ks][3]);
        }
    }
    __syncthreads();   // Q smem free -> pipeline may overwrite

    const __nv_bfloat16* Khb = g_Kh + (size_t)bh * 2048 * 64;
    const __nv_bfloat16* Klb = g_Kl + (size_t)bh * 2048 * 64;
    const __nv_bfloat16* Vhb = g_Vh + (size_t)bh * 2048 * 64;
    const __nv_bfloat16* Vlb = g_Vl + (size_t)bh * 2048 * 64;

    attn_prefetch(sb, 0, tid, Khb, Klb, Vhb, Vlb);
    cpcommit();

    float O[8][4] = {};
    float lsum[2] = {};
    int rbase = qt * 256 + w * 16 + (lane >> 2);
    int kmax = 2 * qt + 1;   // last live kv tile for this q tile

    for (int kt = 0; kt < 16; kt++) {
        if (kt < 15) {
            size_t off = (size_t)(kt + 1) * 128 * 64;
            attn_prefetch(sb, (kt + 1) & 1, tid, Khb + off, Klb + off, Vhb + off, Vlb + off);
            cpcommit();
            cpwait1();
        } else {
            cpwait0();
        }
        __syncthreads();

        uint32_t sK = sb + (kt & 1) * STAGE;
        uint32_t sKl = sK + REG, sV = sK + 2 * REG, sVl = sK + 3 * REG;
        bool live = (kt <= kmax);
        int cb = kt * 128 + 2 * (lane & 3);

        #pragma unroll
        for (int k2 = 0; k2 < 8; k2++) {
            // ---- S slice: 16 rows x 16 cols
            float S[2][4] = {};
            #pragma unroll
            for (int ks = 0; ks < 4; ks++) {
                int row = k2 * 16 + ((lane >> 4) << 3) + (lane & 7);
                int c8 = ks * 2 + ((lane >> 3) & 1);
                uint32_t d = swoff(row, c8);
                uint32_t h0, h1, h2, h3, l0, l1, l2, l3;
                ldsm_x4(sK + d,  h0, h1, h2, h3);
                ldsm_x4(sKl + d, l0, l1, l2, l3);
                mma16816(S[0], qh[ks], h0, h1);
                mma16816(S[0], qh[ks], l0, l1);
                mma16816(S[0], ql[ks], h0, h1);
                mma16816(S[1], qh[ks], h2, h3);
                mma16816(S[1], qh[ks], l2, l3);
                mma16816(S[1], ql[ks], h2, h3);
            }
            // ---- exp + full-row lsum + post-softmax tril mask
            #pragma unroll
            for (int ntl = 0; ntl < 2; ntl++) {
                int colg = cb + k2 * 16 + ntl * 8;
                #pragma unroll
                for (int hf = 0; hf < 2; hf++) {
                    int rg = rbase + 8 * hf;
                    float e0 = fast_exp(S[ntl][2 * hf + 0]);
                    float e1 = fast_exp(S[ntl][2 * hf + 1]);
                    lsum[hf] += e0 + e1;
                    S[ntl][2 * hf + 0] = (colg     <= rg) ? e0 : 0.f;
                    S[ntl][2 * hf + 1] = (colg + 1 <= rg) ? e1 : 0.f;
                }
            }
            // ---- PV for this 16-wide k-slice
            if (live) {
                uint32_t pah[4], pal[4];
                split2(S[0][0], S[0][1], pah[0], pal[0]);
                split2(S[0][2], S[0][3], pah[1], pal[1]);
                split2(S[1][0], S[1][1], pah[2], pal[2]);
                split2(S[1][2], S[1][3], pah[3], pal[3]);
                #pragma unroll
                for (int ntp = 0; ntp < 4; ntp++) {
                    int row = k2 * 16 + lm;
                    int c8 = ntp * 2 + (lane >> 4);
                    uint32_t d = swoff(row, c8);
                    uint32_t v0, v1, v2, v3, u0, u1, u2, u3;
                    ldsm_x4t(sV + d,  v0, v1, v2, v3);
                    ldsm_x4t(sVl + d, u0, u1, u2, u3);
                    mma16816(O[2 * ntp],     pah, v0, v1);
                    mma16816(O[2 * ntp],     pah, u0, u1);
                    mma16816(O[2 * ntp],     pal, v0, v1);
                    mma16816(O[2 * ntp + 1], pah, v2, v3);
                    mma16816(O[2 * ntp + 1], pah, u2, u3);
                    mma16816(O[2 * ntp + 1], pal, v2, v3);
                }
            }
        }
        __syncthreads();   // compute done before next prefetch overwrites other stage
    }

    // ---- row denominators: quad butterfly
    #pragma unroll
    for (int hf = 0; hf < 2; hf++) {
        lsum[hf] += __shfl_xor_sync(0xffffffffu, lsum[hf], 1);
        lsum[hf] += __shfl_xor_sync(0xffffffffu, lsum[hf], 2);
    }

    // ---- write out
    #pragma unroll
    for (int hf = 0; hf < 2; hf++) {
        float inv = 1.0f / lsum[hf];
        int rg = rbase + 8 * hf;
        float* ob = out + ((size_t)b * 2048 + rg) * 1024 + h * 64;
        #pragma unroll
        for (int nt = 0; nt < 8; nt++) {
            int c = nt * 8 + 2 * (lane & 3);
            *(float2*)&ob[c] = make_float2(O[nt][2 * hf] * inv, O[nt][2 * hf + 1] * inv);
        }
    }
}

extern "C" void kernel_launch(void* const* d_in, const int* in_sizes, int n_in,
                              void* d_out, int out_size) {
    const float* X  = (const float*)d_in[0];
    const float* Wq = (const float*)d_in[1];
    const float* bq = (const float*)d_in[2];
    const float* Wk = (const float*)d_in[3];
    const float* bk = (const float*)d_in[4];
    const float* Wv = (const float*)d_in[5];
    const float* bv = (const float*)d_in[6];

    cudaFuncSetAttribute(qkv_mm, cudaFuncAttributeMaxDynamicSharedMemorySize, QKV_SMEM);
    cudaFuncSetAttribute(attn,   cudaFuncAttributeMaxDynamicSharedMemorySize, A_SMEM);

    prep_x<<<4096, 256>>>(X);
    prep_w<<<dim3(32, 2, 48), dim3(32, 8)>>>(Wq, Wk, Wv);
    qkv_mm<<<dim3(32, 16, 3), 256, QKV_SMEM>>>(bq, bk, bv);
    attn<<<256, 512, A_SMEM>>>((float*)d_out);
}

// round 7
// speedup vs baseline: 2.7462x; 1.0533x over previous
#include <cuda_runtime.h>
#include <cuda_bf16.h>
#include <cstdint>

// ---------------- scratch (device globals) ----------------
__device__ __align__(16) __nv_bfloat16 g_Xh[4096*1024], g_Xl[4096*1024];
__device__ __align__(16) __nv_bfloat16 g_Wh[3*1024*1024], g_Wl[3*1024*1024];
__device__ __align__(16) __nv_bfloat16 g_Qh[32*2048*64], g_Ql[32*2048*64];
__device__ __align__(16) __nv_bfloat16 g_Kh[32*2048*64], g_Kl[32*2048*64];
__device__ __align__(16) __nv_bfloat16 g_Vh[32*2048*64], g_Vl[32*2048*64];

// ---------------- helpers ----------------
__device__ __forceinline__ uint32_t smem_u32(const void* p) {
    uint32_t a;
    asm("{ .reg .u64 t; cvta.to.shared.u64 t, %1; cvt.u32.u64 %0, t; }" : "=r"(a) : "l"(p));
    return a;
}
__device__ __forceinline__ uint32_t packbf(__nv_bfloat16 a, __nv_bfloat16 b) {
    return (uint32_t)*(uint16_t*)&a | ((uint32_t)*(uint16_t*)&b << 16);
}
__device__ __forceinline__ void split2(float a, float b, uint32_t& hw, uint32_t& lw) {
    __nv_bfloat16 ha = __float2bfloat16(a), hb = __float2bfloat16(b);
    hw = packbf(ha, hb);
    lw = packbf(__float2bfloat16(a - __bfloat162float(ha)),
                __float2bfloat16(b - __bfloat162float(hb)));
}
__device__ __forceinline__ float fast_exp(float x) {
    float y = fmaxf(x * 1.4426950408889634f, -100.0f);
    float z = y + 12582912.0f;
    int   n = __float_as_int(z) - 0x4B400000;
    float f = y - (z - 12582912.0f);
    float p = 1.33335581e-3f;
    p = fmaf(p, f, 9.61812911e-3f);
    p = fmaf(p, f, 5.55041087e-2f);
    p = fmaf(p, f, 2.40226507e-1f);
    p = fmaf(p, f, 6.93147181e-1f);
    p = fmaf(p, f, 1.0f);
    return __int_as_float(__float_as_int(p) + (n << 23));
}
__device__ __forceinline__ void ldsm_x4(uint32_t a, uint32_t& r0, uint32_t& r1,
                                        uint32_t& r2, uint32_t& r3) {
    asm volatile("ldmatrix.sync.aligned.m8n8.x4.shared.b16 {%0,%1,%2,%3}, [%4];"
        : "=r"(r0), "=r"(r1), "=r"(r2), "=r"(r3) : "r"(a));
}
__device__ __forceinline__ void ldsm_x4t(uint32_t a, uint32_t& r0, uint32_t& r1,
                                         uint32_t& r2, uint32_t& r3) {
    asm volatile("ldmatrix.sync.aligned.m8n8.x4.trans.shared.b16 {%0,%1,%2,%3}, [%4];"
        : "=r"(r0), "=r"(r1), "=r"(r2), "=r"(r3) : "r"(a));
}
__device__ __forceinline__ void mma16816(float* c, const uint32_t* a,
                                         uint32_t b0, uint32_t b1) {
    asm volatile("mma.sync.aligned.m16n8k16.row.col.f32.bf16.bf16.f32 "
        "{%0,%1,%2,%3}, {%4,%5,%6,%7}, {%8,%9}, {%0,%1,%2,%3};"
        : "+f"(c[0]), "+f"(c[1]), "+f"(c[2]), "+f"(c[3])
        : "r"(a[0]), "r"(a[1]), "r"(a[2]), "r"(a[3]), "r"(b0), "r"(b1));
}
__device__ __forceinline__ void cpa16(uint32_t dst, const void* src) {
    asm volatile("cp.async.cg.shared.global [%0], [%1], 16;" :: "r"(dst), "l"(src));
}
__device__ __forceinline__ void cpcommit() { asm volatile("cp.async.commit_group;"); }
__device__ __forceinline__ void cpwait1()  { asm volatile("cp.async.wait_group 1;"); }
__device__ __forceinline__ void cpwait0()  { asm volatile("cp.async.wait_group 0;"); }

// ---------------- prep: split X ----------------
__global__ __launch_bounds__(256) void prep_x(const float* __restrict__ X) {
    size_t i = (size_t)blockIdx.x * 256 + threadIdx.x;
    float4 v = ((const float4*)X)[i];
    uint32_t h0, l0, h1, l1;
    split2(v.x, v.y, h0, l0);
    split2(v.z, v.w, h1, l1);
    ((uint2*)g_Xh)[i] = make_uint2(h0, h1);
    ((uint2*)g_Xl)[i] = make_uint2(l0, l1);
}

// ---------------- prep: transpose+split W -> [mat][h*64+e][d] ----------------
__global__ __launch_bounds__(256) void prep_w(const float* __restrict__ Wq,
                                              const float* __restrict__ Wk,
                                              const float* __restrict__ Wv) {
    int z = blockIdx.z, mat = z >> 4, h = z & 15;
    const float* W = (mat == 0 ? Wq : (mat == 1 ? Wk : Wv)) + (size_t)h * 1024 * 64;
    __shared__ float t[32][33];
    int d0 = blockIdx.x * 32, e0 = blockIdx.y * 32;
    int tx = threadIdx.x, ty = threadIdx.y;
    #pragma unroll
    for (int k = 0; k < 4; k++)
        t[ty + 8 * k][tx] = W[(size_t)(d0 + ty + 8 * k) * 64 + e0 + tx];
    __syncthreads();
    __nv_bfloat16* oh = g_Wh + (size_t)mat * 1048576;
    __nv_bfloat16* ol = g_Wl + (size_t)mat * 1048576;
    #pragma unroll
    for (int k = 0; k < 4; k++) {
        int j = ty + 8 * k;
        float v = t[tx][j];
        __nv_bfloat16 hv = __float2bfloat16(v);
        size_t o = (size_t)(h * 64 + e0 + j) * 1024 + d0 + tx;
        oh[o] = hv;
        ol[o] = __float2bfloat16(v - __bfloat162float(hv));
    }
}

// ---------------- QKV GEMM: 128x64 CTA tile, cp.async double buffer ----------------
#define GP 40
#define QKV_SMEM (2 * 15360 * 2)

__device__ __forceinline__ void qkv_prefetch(uint32_t sb, int st, int stile, int octile,
                                             int kc, int tid,
                                             const __nv_bfloat16* Bh,
                                             const __nv_bfloat16* Bl) {
    uint32_t s0 = sb + st * 15360 * 2;
    #pragma unroll
    for (int i = tid; i < 512; i += 256) {
        int r = i >> 2, c8 = i & 3;
        uint32_t d = s0 + (r * GP + c8 * 8) * 2;
        size_t g = (size_t)(stile * 128 + r) * 1024 + kc * 32 + c8 * 8;
        cpa16(d, g_Xh + g);
        cpa16(d + 5120 * 2, g_Xl + g);
    }
    {
        int i = tid;
        int r = i >> 2, c8 = i & 3;
        uint32_t d = s0 + (10240 + r * GP + c8 * 8) * 2;
        size_t g = (size_t)(octile * 64 + r) * 1024 + kc * 32 + c8 * 8;
        cpa16(d, Bh + g);
        cpa16(d + 2560 * 2, Bl + g);
    }
}

__global__ __launch_bounds__(256, 2) void qkv_mm(const float* __restrict__ bq,
                                                 const float* __restrict__ bk,
                                                 const float* __restrict__ bv) {
    extern __shared__ __align__(16) __nv_bfloat16 smq[];
    uint32_t sb = smem_u32(smq);
    int tid = threadIdx.x, lane = tid & 31, wid = tid >> 5;
    int stile = blockIdx.x, octile = blockIdx.y, mat = blockIdx.z;
    int wm = wid >> 1, wn = wid & 1;
    int lm = lane & 15;

    const __nv_bfloat16* Bh = g_Wh + (size_t)mat * 1048576;
    const __nv_bfloat16* Bl = g_Wl + (size_t)mat * 1048576;

    float C[2][4][4] = {};

    qkv_prefetch(sb, 0, stile, octile, 0, tid, Bh, Bl);
    cpcommit();

    for (int kc = 0; kc < 32; kc++) {
        if (kc < 31) {
            qkv_prefetch(sb, (kc + 1) & 1, stile, octile, kc + 1, tid, Bh, Bl);
            cpcommit();
            cpwait1();
        } else {
            cpwait0();
        }
        __syncthreads();
        uint32_t bufA = sb + (kc & 1) * 15360 * 2;
        uint32_t bufBh = bufA + 10240 * 2, bufBl = bufA + 12800 * 2;
        #pragma unroll
        for (int ks = 0; ks < 2; ks++) {
            uint32_t ah[2][4], al[2][4];
            #pragma unroll
            for (int mt = 0; mt < 2; mt++) {
                uint32_t off = ((uint32_t)(wm * 32 + mt * 16 + lm) * GP
                                + ks * 16 + ((lane >> 4) << 3)) * 2;
                ldsm_x4(bufA + off, ah[mt][0], ah[mt][1], ah[mt][2], ah[mt][3]);
                ldsm_x4(bufA + 5120 * 2 + off, al[mt][0], al[mt][1], al[mt][2], al[mt][3]);
            }
            #pragma unroll
            for (int ntp = 0; ntp < 2; ntp++) {
                uint32_t off = ((uint32_t)(wn * 32 + ntp * 16 + ((lane >> 4) << 3) + (lane & 7)) * GP
                                + ks * 16 + (((lane >> 3) & 1) << 3)) * 2;
                uint32_t h0, h1, h2, h3, l0, l1, l2, l3;
                ldsm_x4(bufBh + off, h0, h1, h2, h3);
                ldsm_x4(bufBl + off, l0, l1, l2, l3);
                #pragma unroll
                for (int mt = 0; mt < 2; mt++) {
                    mma16816(C[mt][2 * ntp],     ah[mt], h0, h1);
                    mma16816(C[mt][2 * ntp],     ah[mt], l0, l1);
                    mma16816(C[mt][2 * ntp],     al[mt], h0, h1);
                    mma16816(C[mt][2 * ntp + 1], ah[mt], h2, h3);
                    mma16816(C[mt][2 * ntp + 1], ah[mt], l2, l3);
                    mma16816(C[mt][2 * ntp + 1], al[mt], h2, h3);
                }
            }
        }
        __syncthreads();
    }

    const float* bias = (mat == 0 ? bq : (mat == 1 ? bk : bv));
    float scale = (mat == 0) ? 0.125f : 1.0f;
    __nv_bfloat16* Dh = (mat == 0 ? g_Qh : (mat == 1 ? g_Kh : g_Vh));
    __nv_bfloat16* Dl = (mat == 0 ? g_Ql : (mat == 1 ? g_Kl : g_Vl));
    #pragma unroll
    for (int mt = 0; mt < 2; mt++) {
        #pragma unroll
        for (int nt = 0; nt < 4; nt++) {
            int col = octile * 64 + wn * 32 + nt * 8 + 2 * (lane & 3);
            float b0 = __ldg(bias + col), b1 = __ldg(bias + col + 1);
            int hh = col >> 6, e = col & 63;
            #pragma unroll
            for (int hf = 0; hf < 2; hf++) {
                int row = stile * 128 + wm * 32 + mt * 16 + (lane >> 2) + 8 * hf;
                float v0 = (C[mt][nt][2 * hf + 0] + b0) * scale;
                float v1 = (C[mt][nt][2 * hf + 1] + b1) * scale;
                uint32_t hw, lw;
                split2(v0, v1, hw, lw);
                int b = row >> 11, s = row & 2047;
                size_t o = ((size_t)(b * 16 + hh) * 2048 + s) * 64 + e;
                *(uint32_t*)&Dh[o] = hw;
                *(uint32_t*)&Dl[o] = lw;
            }
        }
    }
}

// ---------------- attention: 256 thr / 128 q-rows / 64-row kv tiles, 2 CTAs/SM ----------------
#define REG 8192                       // region: 64 rows x 64 bf16 = 8KB
#define STAGE (4 * REG)                // KH KL VH VL = 32KB
#define A_SMEM (2 * STAGE)             // 64KB

// swizzled byte offset within a region: row r (0..63), 16B chunk c8 (0..7)
__device__ __forceinline__ uint32_t swoff(int r, int c8) {
    return (uint32_t)(((r << 3) + (c8 ^ (r & 7))) << 4);
}

// prefetch one 64-row kv tile; masked tiles need only K-hi (denominator path)
__device__ __forceinline__ void attn_prefetch(uint32_t s0, int tid,
                                              const __nv_bfloat16* Kh,
                                              const __nv_bfloat16* Kl,
                                              const __nv_bfloat16* Vh,
                                              const __nv_bfloat16* Vl, bool full) {
    #pragma unroll
    for (int i = tid; i < 512; i += 256) {
        int r = i >> 3, c8 = i & 7;
        uint32_t d = swoff(r, c8);
        size_t g = (size_t)r * 64 + c8 * 8;
        cpa16(s0 + d, Kh + g);
        if (full) {
            cpa16(s0 + REG + d,     Kl + g);
            cpa16(s0 + 2 * REG + d, Vh + g);
            cpa16(s0 + 3 * REG + d, Vl + g);
        }
    }
}

// S slice (16 rows x 16 cols): 3-term for live tiles, 2-term (q full x K-hi) for masked
__device__ __forceinline__ void compS(uint32_t sK, uint32_t sKl, int k2, int lane,
                                      const uint32_t qh[4][4], const uint32_t ql[4][4],
                                      bool full, float S[2][4]) {
    #pragma unroll
    for (int z = 0; z < 4; z++) { S[0][z] = 0.f; S[1][z] = 0.f; }
    #pragma unroll
    for (int ks = 0; ks < 4; ks++) {
        int row = k2 * 16 + ((lane >> 4) << 3) + (lane & 7);
        int c8 = ks * 2 + ((lane >> 3) & 1);
        uint32_t d = swoff(row, c8);
        uint32_t h0, h1, h2, h3;
        ldsm_x4(sK + d, h0, h1, h2, h3);
        if (full) {
            uint32_t l0, l1, l2, l3;
            ldsm_x4(sKl + d, l0, l1, l2, l3);
            mma16816(S[0], qh[ks], h0, h1);
            mma16816(S[0], qh[ks], l0, l1);
            mma16816(S[0], ql[ks], h0, h1);
            mma16816(S[1], qh[ks], h2, h3);
            mma16816(S[1], qh[ks], l2, l3);
            mma16816(S[1], ql[ks], h2, h3);
        } else {
            mma16816(S[0], qh[ks], h0, h1);
            mma16816(S[0], ql[ks], h0, h1);
            mma16816(S[1], qh[ks], h2, h3);
            mma16816(S[1], ql[ks], h2, h3);
        }
    }
}

__global__ __launch_bounds__(256, 2) void attn(float* __restrict__ out) {
    extern __shared__ __align__(16) char sm[];
    uint32_t sb = smem_u32(sm);
    int tid = threadIdx.x, lane = tid & 31, w = tid >> 5;
    int bh = blockIdx.x >> 4, qt = 15 - (blockIdx.x & 15);   // heavy-first
    int b = bh >> 4, h = bh & 15;
    int lm = lane & 15;

    // ---- stage Q (128x64 h/l) through stage-0 buffer, extract fragments, recycle
    const __nv_bfloat16* Qh = g_Qh + ((size_t)bh * 2048 + qt * 128) * 64;
    const __nv_bfloat16* Ql = g_Ql + ((size_t)bh * 2048 + qt * 128) * 64;
    #pragma unroll
    for (int i = tid; i < 1024; i += 256) {
        int r = i >> 3, c8 = i & 7;
        uint32_t d = ((r >= 64) ? REG : 0) + swoff(r & 63, c8);
        size_t g = (size_t)r * 64 + c8 * 8;
        cpa16(sb + d,           Qh + g);
        cpa16(sb + 2 * REG + d, Ql + g);
    }
    cpcommit(); cpwait0();
    __syncthreads();

    uint32_t qh[4][4], ql[4][4];
    {
        uint32_t qreg = (w >= 4) ? REG : 0;
        int rowb = (w & 3) * 16 + lm;
        #pragma unroll
        for (int ks = 0; ks < 4; ks++) {
            int c8 = ks * 2 + (lane >> 4);
            uint32_t d = swoff(rowb, c8);
            ldsm_x4(sb + qreg + d,           qh[ks][0], qh[ks][1], qh[ks][2], qh[ks][3]);
            ldsm_x4(sb + qreg + 2 * REG + d, ql[ks][0], ql[ks][1], ql[ks][2], ql[ks][3]);
        }
    }
    __syncthreads();   // Q smem free -> pipeline may overwrite

    const __nv_bfloat16* Khb = g_Kh + (size_t)bh * 2048 * 64;
    const __nv_bfloat16* Klb = g_Kl + (size_t)bh * 2048 * 64;
    const __nv_bfloat16* Vhb = g_Vh + (size_t)bh * 2048 * 64;
    const __nv_bfloat16* Vlb = g_Vl + (size_t)bh * 2048 * 64;

    int kmax = 2 * qt + 1;   // last live 64-row kv tile
    attn_prefetch(sb, tid, Khb, Klb, Vhb, Vlb, true);   // kt=0 always live
    cpcommit();

    float O[8][4] = {};
    float lsum[2] = {};
    int rbase = qt * 128 + w * 16 + (lane >> 2);

    for (int kt = 0; kt < 32; kt++) {
        if (kt < 31) {
            size_t off = (size_t)(kt + 1) * 64 * 64;
            attn_prefetch(sb + ((kt + 1) & 1) * STAGE, tid,
                          Khb + off, Klb + off, Vhb + off, Vlb + off, (kt + 1) <= kmax);
            cpcommit();
            cpwait1();
        } else {
            cpwait0();
        }
        __syncthreads();

        uint32_t sK = sb + (kt & 1) * STAGE;
        uint32_t sKl = sK + REG, sV = sK + 2 * REG, sVl = sK + 3 * REG;
        bool live = (kt <= kmax);
        int cb = kt * 64 + 2 * (lane & 3);

        float Sc[2][4];
        compS(sK, sKl, 0, lane, qh, ql, live, Sc);

        #pragma unroll
        for (int k2 = 0; k2 < 4; k2++) {
            // software pipeline: next slice's S MMAs fill tensor pipe during exp/PV
            float Sn[2][4];
            if (k2 < 3) compS(sK, sKl, k2 + 1, lane, qh, ql, live, Sn);

            // ---- exp + full-row lsum + post-softmax tril mask
            #pragma unroll
            for (int ntl = 0; ntl < 2; ntl++) {
                int colg = cb + k2 * 16 + ntl * 8;
                #pragma unroll
                for (int hf = 0; hf < 2; hf++) {
                    int rg = rbase + 8 * hf;
                    float e0 = fast_exp(Sc[ntl][2 * hf + 0]);
                    float e1 = fast_exp(Sc[ntl][2 * hf + 1]);
                    lsum[hf] += e0 + e1;
                    Sc[ntl][2 * hf + 0] = (colg     <= rg) ? e0 : 0.f;
                    Sc[ntl][2 * hf + 1] = (colg + 1 <= rg) ? e1 : 0.f;
                }
            }
            // ---- PV for this 16-wide k-slice
            if (live) {
                uint32_t pah[4], pal[4];
                split2(Sc[0][0], Sc[0][1], pah[0], pal[0]);
                split2(Sc[0][2], Sc[0][3], pah[1], pal[1]);
                split2(Sc[1][0], Sc[1][1], pah[2], pal[2]);
                split2(Sc[1][2], Sc[1][3], pah[3], pal[3]);
                #pragma unroll
                for (int ntp = 0; ntp < 4; ntp++) {
                    int row = k2 * 16 + lm;
                    int c8 = ntp * 2 + (lane >> 4);
                    uint32_t d = swoff(row, c8);
                    uint32_t v0, v1, v2, v3, u0, u1, u2, u3;
                    ldsm_x4t(sV + d,  v0, v1, v2, v3);
                    ldsm_x4t(sVl + d, u0, u1, u2, u3);
                    mma16816(O[2 * ntp],     pah, v0, v1);
                    mma16816(O[2 * ntp],     pah, u0, u1);
                    mma16816(O[2 * ntp],     pal, v0, v1);
                    mma16816(O[2 * ntp + 1], pah, v2, v3);
                    mma16816(O[2 * ntp + 1], pah, u2, u3);
                    mma16816(O[2 * ntp + 1], pal, v2, v3);
                }
            }
            if (k2 < 3) {
                #pragma unroll
                for (int ntl = 0; ntl < 2; ntl++)
                    #pragma unroll
                    for (int z = 0; z < 4; z++) Sc[ntl][z] = Sn[ntl][z];
            }
        }
        __syncthreads();   // compute done before next prefetch overwrites other stage
    }

    // ---- row denominators: quad butterfly (warp-local rows)
    #pragma unroll
    for (int hf = 0; hf < 2; hf++) {
        lsum[hf] += __shfl_xor_sync(0xffffffffu, lsum[hf], 1);
        lsum[hf] += __shfl_xor_sync(0xffffffffu, lsum[hf], 2);
    }

    // ---- write out
    #pragma unroll
    for (int hf = 0; hf < 2; hf++) {
        float inv = 1.0f / lsum[hf];
        int rg = rbase + 8 * hf;
        float* ob = out + ((size_t)b * 2048 + rg) * 1024 + h * 64;
        #pragma unroll
        for (int nt = 0; nt < 8; nt++) {
            int c = nt * 8 + 2 * (lane & 3);
            *(float2*)&ob[c] = make_float2(O[nt][2 * hf] * inv, O[nt][2 * hf + 1] * inv);
        }
    }
}

extern "C" void kernel_launch(void* const* d_in, const int* in_sizes, int n_in,
                              void* d_out, int out_size) {
    const float* X  = (const float*)d_in[0];
    const float* Wq = (const float*)d_in[1];
    const float* bq = (const float*)d_in[2];
    const float* Wk = (const float*)d_in[3];
    const float* bk = (const float*)d_in[4];
    const float* Wv = (const float*)d_in[5];
    const float* bv = (const float*)d_in[6];

    cudaFuncSetAttribute(qkv_mm, cudaFuncAttributeMaxDynamicSharedMemorySize, QKV_SMEM);
    cudaFuncSetAttribute(attn,   cudaFuncAttributeMaxDynamicSharedMemorySize, A_SMEM);

    prep_x<<<4096, 256>>>(X);
    prep_w<<<dim3(32, 2, 48), dim3(32, 8)>>>(Wq, Wk, Wv);
    qkv_mm<<<dim3(32, 16, 3), 256, QKV_SMEM>>>(bq, bk, bv);
    attn<<<512, 256, A_SMEM>>>((float*)d_out);
}